// round 3
// baseline (speedup 1.0000x reference)
#include <cuda_runtime.h>
#include <math.h>

// Problem constants
#define Bsz  4
#define Nseq 8192
#define Dm   1024
#define Hh   8
#define HDim 128
#define BH   (Bsz*Hh)        // 32
#define Mrows (Bsz*Nseq)     // 32768
#define K3   (3*Dm)          // 3072
#define NCHUNK 32            // N split for kv reduction

// ---------------- scratch (static device globals; no allocations) -------------
__device__ float g_mu[Mrows];
__device__ float g_rstd[Mrows];
__device__ float g_w2[Dm*K3];            // gamma-folded weights   (12.6 MB)
__device__ float g_cbias[K3];            // beta-folded column bias
__device__ float g_q[(size_t)BH*Nseq*HDim];   // 134 MB
__device__ float g_k[(size_t)BH*Nseq*HDim];   // 134 MB
__device__ float g_v[(size_t)BH*Nseq*HDim];   // 134 MB
__device__ float g_kvp[(size_t)BH*NCHUNK*HDim*HDim]; // 67 MB partials
__device__ float g_kv[(size_t)BH*HDim*HDim];         // 2 MB
__device__ unsigned int  g_flag;                      // mask-layout flag
__device__ unsigned char g_mask[Bsz*Nseq];            // canonical mask (0/1)

// ---------------- 0) mask layout probe + normalization -----------------------
// The mask is logically bool [B,1,N]. The harness may materialize it as int32
// (one word per element) or as packed bytes. Classify on-device, normalize to
// canonical uint8. Deterministic: depends only on input bytes; flag is reset
// every call so graph replays are identical.
__global__ void mask_reset_kernel() { g_flag = 0u; }

__global__ void mask_probe_kernel(const unsigned int* __restrict__ m) {
    // Examine first 8192 int32 words (= full buffer if byte layout).
    int i = blockIdx.x*256 + threadIdx.x;           // grid 32 -> 8192 words
    if (m[i] > 1u) atomicOr(&g_flag, 1u);           // impossible for int32 0/1 layout
}

__global__ void mask_norm_kernel(const void* __restrict__ m) {
    int i = blockIdx.x*256 + threadIdx.x;           // grid 128 -> 32768 elems
    unsigned char r;
    if (g_flag) r = ((const unsigned char*)m)[i] ? 1 : 0;   // byte layout
    else        r = ((const int*)m)[i]           ? 1 : 0;   // int32 layout
    g_mask[i] = r;
}

// ---------------- 1) LayerNorm row statistics --------------------------------
__global__ void ln_stats_kernel(const float* __restrict__ x) {
    int row = blockIdx.x;
    float4 v = reinterpret_cast<const float4*>(x)[(size_t)row*(Dm/4) + threadIdx.x];
    float s  = v.x+v.y+v.z+v.w;
    float ss = v.x*v.x+v.y*v.y+v.z*v.z+v.w*v.w;
    __shared__ float sh[8], sh2[8];
    #pragma unroll
    for (int o=16;o;o>>=1){ s+=__shfl_down_sync(~0u,s,o); ss+=__shfl_down_sync(~0u,ss,o); }
    int w = threadIdx.x>>5, l = threadIdx.x&31;
    if (l==0){ sh[w]=s; sh2[w]=ss; }
    __syncthreads();
    if (threadIdx.x < 8) {
        s = sh[threadIdx.x]; ss = sh2[threadIdx.x];
        #pragma unroll
        for (int o=4;o;o>>=1){ s+=__shfl_down_sync(0xffu,s,o); ss+=__shfl_down_sync(0xffu,ss,o); }
        if (threadIdx.x==0){
            float m = s*(1.0f/Dm);
            float var = ss*(1.0f/Dm) - m*m;
            g_mu[row]   = m;
            g_rstd[row] = rsqrtf(var + 1e-5f);
        }
    }
}

// ---------------- 2) fold gamma into W, beta into column bias ----------------
__global__ void prep_w_kernel(const float* __restrict__ w, const float* __restrict__ gamma) {
    int i = blockIdx.x*256 + threadIdx.x;   // grid = Dm*K3/256
    g_w2[i] = w[i] * gamma[i / K3];
}
__global__ void colbias_kernel(const float* __restrict__ w, const float* __restrict__ beta) {
    int c = blockIdx.x*256 + threadIdx.x;   // grid = K3/256
    float s = 0.f;
    for (int k = 0; k < Dm; k++) s += beta[k]*w[(size_t)k*K3 + c];
    g_cbias[c] = s;
}

// ---------------- 3) fused LN + QKV GEMM + activations + scatter -------------
// C[M=32768, 3072] = ((x - mu)*rstd) @ g_w2 + cbias ; then sigmoid/tanh+mask/id
// Tile 128x128x8, 256 threads, 8x8 per-thread register tile.
__global__ void __launch_bounds__(256,2) gemm_qkv_kernel(const float* __restrict__ x)
{
    __shared__ float As[8][128];
    __shared__ float Bs[8][128];
    const int tid = threadIdx.x;
    const int bn  = blockIdx.x;        // 0..23  (column tile)
    const int bm  = blockIdx.y;        // 0..255 (row tile)
    const int m0  = bm*128;

    const int arow = tid>>1,  acol = (tid&1)*4;
    const int brow = tid>>5,  bcol = (tid&31)*4;
    const float* Ap = x    + (size_t)(m0+arow)*Dm + acol;
    const float* Bp = g_w2 + (size_t)brow*K3 + bn*128 + bcol;
    const float mrow = g_mu[m0+arow];
    const float rrow = g_rstd[m0+arow];

    float acc[8][8];
    #pragma unroll
    for (int i=0;i<8;i++)
        #pragma unroll
        for (int j=0;j<8;j++) acc[i][j]=0.f;

    const int ty = tid>>4, tx = tid&15;

    for (int kt = 0; kt < Dm/8; kt++) {
        float4 av = *(const float4*)(Ap + kt*8);
        float4 bv = *(const float4*)(Bp + (size_t)kt*8*K3);
        av.x = (av.x - mrow)*rrow; av.y = (av.y - mrow)*rrow;
        av.z = (av.z - mrow)*rrow; av.w = (av.w - mrow)*rrow;
        As[acol+0][arow]=av.x; As[acol+1][arow]=av.y;
        As[acol+2][arow]=av.z; As[acol+3][arow]=av.w;
        *(float4*)&Bs[brow][bcol] = bv;
        __syncthreads();
        #pragma unroll
        for (int kk=0; kk<8; kk++){
            float ar[8], br[8];
            *(float4*)&ar[0] = *(const float4*)&As[kk][ty*8];
            *(float4*)&ar[4] = *(const float4*)&As[kk][ty*8+4];
            *(float4*)&br[0] = *(const float4*)&Bs[kk][tx*8];
            *(float4*)&br[4] = *(const float4*)&Bs[kk][tx*8+4];
            #pragma unroll
            for (int i=0;i<8;i++)
                #pragma unroll
                for (int j=0;j<8;j++)
                    acc[i][j] = fmaf(ar[i], br[j], acc[i][j]);
        }
        __syncthreads();
    }

    // epilogue: whole block lies in one of q/k/v and one head
    const int which = bn>>3;           // 0=q 1=k 2=v
    const int h = bn&7;
    const int b = m0>>13;              // m0 / 8192
    const int n0 = (m0 & (Nseq-1)) + ty*8;
    const int e0 = tx*8;
    float* dst = (which==0) ? g_q : (which==1) ? g_k : g_v;

    float cb[8];
    #pragma unroll
    for (int j=0;j<8;j++) cb[j] = g_cbias[bn*128 + e0 + j];

    #pragma unroll
    for (int i=0;i<8;i++){
        int n = n0 + i;
        float mfac = 1.f;
        if (which==1) mfac = g_mask[(size_t)b*Nseq + n] ? 0.f : 1.f;
        float outv[8];
        #pragma unroll
        for (int j=0;j<8;j++){
            float vv = acc[i][j] + cb[j];
            if      (which==0) vv = 1.f/(1.f + __expf(-vv));
            else if (which==1) vv = tanhf(vv)*mfac;
            outv[j] = vv;
        }
        float* p = dst + ((size_t)(b*Hh+h)*Nseq + n)*HDim + e0;
        *(float4*)p     = *(float4*)&outv[0];
        *(float4*)(p+4) = *(float4*)&outv[4];
    }
}

// ---------------- 4) kv partials: per (bh, chunk) 128x128 = k^T v ------------
__global__ void __launch_bounds__(256,2) kv_partial_kernel() {
    const int ch = blockIdx.x;         // 0..31 (N chunk of 256)
    const int bh = blockIdx.y;         // 0..31
    __shared__ float Ks[8][128], Vs[8][128];
    const int tid = threadIdx.x;
    const int lr = tid>>5, lc = (tid&31)*4;
    const size_t base = ((size_t)bh*Nseq + ch*256)*HDim + (size_t)lr*HDim + lc;
    const float* kp = g_k + base;
    const float* vp = g_v + base;

    float acc[8][8];
    #pragma unroll
    for (int i=0;i<8;i++)
        #pragma unroll
        for (int j=0;j<8;j++) acc[i][j]=0.f;
    const int ty = tid>>4, tx = tid&15;

    for (int s = 0; s < 32; s++) {     // 32 * 8 = 256 tokens
        *(float4*)&Ks[lr][lc] = *(const float4*)(kp + (size_t)s*8*HDim);
        *(float4*)&Vs[lr][lc] = *(const float4*)(vp + (size_t)s*8*HDim);
        __syncthreads();
        #pragma unroll
        for (int kk=0; kk<8; kk++){
            float ar[8], br[8];
            *(float4*)&ar[0] = *(const float4*)&Ks[kk][ty*8];
            *(float4*)&ar[4] = *(const float4*)&Ks[kk][ty*8+4];
            *(float4*)&br[0] = *(const float4*)&Vs[kk][tx*8];
            *(float4*)&br[4] = *(const float4*)&Vs[kk][tx*8+4];
            #pragma unroll
            for (int i=0;i<8;i++)
                #pragma unroll
                for (int j=0;j<8;j++)
                    acc[i][j] = fmaf(ar[i], br[j], acc[i][j]);
        }
        __syncthreads();
    }
    float* p = g_kvp + (size_t)(bh*NCHUNK + ch)*HDim*HDim;
    #pragma unroll
    for (int i=0;i<8;i++){
        float* pp = p + (size_t)(ty*8+i)*HDim + tx*8;
        *(float4*)pp     = *(float4*)&acc[i][0];
        *(float4*)(pp+4) = *(float4*)&acc[i][4];
    }
}

// ---------------- 5) deterministic reduce of kv partials ---------------------
__global__ void kv_reduce_kernel() {
    int bh  = blockIdx.y;
    int idx = blockIdx.x*256 + threadIdx.x;   // grid.x = 64 -> 16384 elems
    float s = 0.f;
    #pragma unroll
    for (int c = 0; c < NCHUNK; c++)
        s += g_kvp[(size_t)(bh*NCHUNK + c)*HDim*HDim + idx];
    g_kv[(size_t)bh*HDim*HDim + idx] = s;
}

// ---------------- 6) out = q @ kv, scatter to [B,N,D] ------------------------
__global__ void __launch_bounds__(256,2) out_kernel(float* __restrict__ out) {
    const int mt = blockIdx.x;         // 0..63 row tile within (b,h)
    const int bh = blockIdx.y;         // 0..31
    const int b = bh>>3, h = bh&7;
    __shared__ float As[8][128], Bs[8][128];
    const int tid = threadIdx.x;
    const int arow = tid>>1,  acol = (tid&1)*4;
    const int brow = tid>>5,  bcol = (tid&31)*4;
    const float* Ap = g_q  + ((size_t)bh*Nseq + mt*128 + arow)*HDim + acol;
    const float* Bp = g_kv + (size_t)bh*HDim*HDim + (size_t)brow*HDim + bcol;

    float acc[8][8];
    #pragma unroll
    for (int i=0;i<8;i++)
        #pragma unroll
        for (int j=0;j<8;j++) acc[i][j]=0.f;
    const int ty = tid>>4, tx = tid&15;

    for (int kt = 0; kt < HDim/8; kt++) {
        float4 av = *(const float4*)(Ap + kt*8);
        As[acol+0][arow]=av.x; As[acol+1][arow]=av.y;
        As[acol+2][arow]=av.z; As[acol+3][arow]=av.w;
        *(float4*)&Bs[brow][bcol] = *(const float4*)(Bp + (size_t)kt*8*HDim);
        __syncthreads();
        #pragma unroll
        for (int kk=0; kk<8; kk++){
            float ar[8], br[8];
            *(float4*)&ar[0] = *(const float4*)&As[kk][ty*8];
            *(float4*)&ar[4] = *(const float4*)&As[kk][ty*8+4];
            *(float4*)&br[0] = *(const float4*)&Bs[kk][tx*8];
            *(float4*)&br[4] = *(const float4*)&Bs[kk][tx*8+4];
            #pragma unroll
            for (int i=0;i<8;i++)
                #pragma unroll
                for (int j=0;j<8;j++)
                    acc[i][j] = fmaf(ar[i], br[j], acc[i][j]);
        }
        __syncthreads();
    }

    #pragma unroll
    for (int i=0;i<8;i++){
        int n = mt*128 + ty*8 + i;
        float* p = out + ((size_t)b*Nseq + n)*Dm + h*HDim + tx*8;
        *(float4*)p     = *(float4*)&acc[i][0];
        *(float4*)(p+4) = *(float4*)&acc[i][4];
    }
}

// ---------------- launch ------------------------------------------------------
extern "C" void kernel_launch(void* const* d_in, const int* in_sizes, int n_in,
                              void* d_out, int out_size) {
    // Resolve inputs by element count (robust to ordering):
    //   x: 33554432, mask: 32768, w_qkv: 3145728, gamma/beta: 1024 (in order)
    const float* x = 0; const void* mask = 0; const float* w = 0;
    const float* gamma = 0; const float* beta = 0;
    for (int i = 0; i < n_in; i++) {
        int s = in_sizes[i];
        if      (s == 33554432) x    = (const float*)d_in[i];
        else if (s == 32768)    mask = d_in[i];
        else if (s == 3145728)  w    = (const float*)d_in[i];
        else if (s == 1024)     { if (!gamma) gamma = (const float*)d_in[i];
                                  else        beta  = (const float*)d_in[i]; }
    }
    float* out = (float*)d_out;

    mask_reset_kernel<<<1, 1>>>();
    mask_probe_kernel<<<32, 256>>>((const unsigned int*)mask);
    mask_norm_kernel<<<128, 256>>>(mask);
    ln_stats_kernel<<<Mrows, 256>>>(x);
    prep_w_kernel<<<(Dm*K3)/256, 256>>>(w, gamma);
    colbias_kernel<<<K3/256, 256>>>(w, beta);
    gemm_qkv_kernel<<<dim3(24, 256), 256>>>(x);
    kv_partial_kernel<<<dim3(NCHUNK, BH), 256>>>();
    kv_reduce_kernel<<<dim3(64, BH), 256>>>();
    out_kernel<<<dim3(64, BH), 256>>>(out);
}

// round 5
// speedup vs baseline: 1.9339x; 1.9339x over previous
#include <cuda_runtime.h>
#include <cuda_bf16.h>
#include <cstdint>
#include <math.h>

// Problem constants
#define Bsz  4
#define Nseq 8192
#define Dm   1024
#define Hh   8
#define HDim 128
#define BH   (Bsz*Hh)        // 32
#define Mrows (Bsz*Nseq)     // 32768
#define K3   (3*Dm)          // 3072 output cols
#define KSPLIT 3072          // split-K contraction length (hi|lo|hi)
#define NCHUNK 32

// ---------------- scratch (static device globals; no allocations) -------------
__device__ __nv_bfloat16 g_a2[(size_t)Mrows*KSPLIT];  // 192 MiB: [hi|lo|hi] per row
__device__ __nv_bfloat16 g_wt[(size_t)K3*KSPLIT];     // 18 MiB:  per col n: [w_hi|w_hi|w_lo]
__device__ float g_cbias[K3];
__device__ float g_q[(size_t)BH*Nseq*HDim];
__device__ float g_k[(size_t)BH*Nseq*HDim];
__device__ float g_v[(size_t)BH*Nseq*HDim];
__device__ float g_kvp[(size_t)BH*NCHUNK*HDim*HDim];
__device__ float g_kv[(size_t)BH*HDim*HDim];
__device__ unsigned int  g_flag;
__device__ unsigned char g_mask[Bsz*Nseq];

// ---------------- 0) mask layout probe + normalization ------------------------
__global__ void mask_reset_kernel() { g_flag = 0u; }
__global__ void mask_probe_kernel(const unsigned int* __restrict__ m) {
    int i = blockIdx.x*256 + threadIdx.x;
    if (m[i] > 1u) atomicOr(&g_flag, 1u);
}
__global__ void mask_norm_kernel(const void* __restrict__ m) {
    int i = blockIdx.x*256 + threadIdx.x;
    unsigned char r;
    if (g_flag) r = ((const unsigned char*)m)[i] ? 1 : 0;
    else        r = ((const int*)m)[i]           ? 1 : 0;
    g_mask[i] = r;
}

// ---------------- 1) fused LN stats + A2 (bf16 hi/lo split) build -------------
__global__ void ln_a2_kernel(const float* __restrict__ x) {
    int row = blockIdx.x;
    float4 v = reinterpret_cast<const float4*>(x)[(size_t)row*(Dm/4) + threadIdx.x];
    float s  = v.x+v.y+v.z+v.w;
    float ss = v.x*v.x+v.y*v.y+v.z*v.z+v.w*v.w;
    __shared__ float sh[8], sh2[8];
    __shared__ float s_mu, s_rs;
    #pragma unroll
    for (int o=16;o;o>>=1){ s+=__shfl_down_sync(~0u,s,o); ss+=__shfl_down_sync(~0u,ss,o); }
    int w = threadIdx.x>>5, l = threadIdx.x&31;
    if (l==0){ sh[w]=s; sh2[w]=ss; }
    __syncthreads();
    if (threadIdx.x < 8) {
        s = sh[threadIdx.x]; ss = sh2[threadIdx.x];
        #pragma unroll
        for (int o=4;o;o>>=1){ s+=__shfl_down_sync(0xffu,s,o); ss+=__shfl_down_sync(0xffu,ss,o); }
        if (threadIdx.x==0){
            float m = s*(1.0f/Dm);
            float var = ss*(1.0f/Dm) - m*m;
            s_mu = m; s_rs = rsqrtf(var + 1e-5f);
        }
    }
    __syncthreads();
    float mu = s_mu, rs = s_rs;
    float n0=(v.x-mu)*rs, n1=(v.y-mu)*rs, n2=(v.z-mu)*rs, n3=(v.w-mu)*rs;
    __nv_bfloat16 h0=__float2bfloat16(n0), h1=__float2bfloat16(n1),
                  h2=__float2bfloat16(n2), h3=__float2bfloat16(n3);
    __nv_bfloat16 l0=__float2bfloat16(n0-__bfloat162float(h0)),
                  l1=__float2bfloat16(n1-__bfloat162float(h1)),
                  l2=__float2bfloat16(n2-__bfloat162float(h2)),
                  l3=__float2bfloat16(n3-__bfloat162float(h3));
    __nv_bfloat162 hp0{h0,h1}, hp1{h2,h3}, lp0{l0,l1}, lp1{l2,l3};
    uint2 hw{*(uint32_t*)&hp0, *(uint32_t*)&hp1};
    uint2 lw{*(uint32_t*)&lp0, *(uint32_t*)&lp1};
    __nv_bfloat16* base = g_a2 + (size_t)row*KSPLIT;
    ((uint2*)base)[threadIdx.x]          = hw;   // k in [0,1024):    hi
    ((uint2*)(base + 1024))[threadIdx.x] = lw;   // k in [1024,2048): lo
    ((uint2*)(base + 2048))[threadIdx.x] = hw;   // k in [2048,3072): hi
}

// ---------------- 2) Wt build: transpose + gamma fold + hi/lo split -----------
__global__ void build_wt_kernel(const float* __restrict__ w, const float* __restrict__ gamma) {
    __shared__ float tile[32][33];
    int n0 = blockIdx.x*32, k0 = blockIdx.y*32;
    int tx = threadIdx.x & 31, ty = threadIdx.x >> 5;  // 32x8
    #pragma unroll
    for (int r=0;r<4;r++){
        int kk = ty + r*8;
        tile[kk][tx] = w[(size_t)(k0+kk)*K3 + n0 + tx] * gamma[k0+kk];
    }
    __syncthreads();
    #pragma unroll
    for (int r=0;r<4;r++){
        int nn = ty + r*8;
        float val = tile[tx][nn];
        __nv_bfloat16 hi = __float2bfloat16(val);
        __nv_bfloat16 lo = __float2bfloat16(val - __bfloat162float(hi));
        __nv_bfloat16* base = g_wt + (size_t)(n0+nn)*KSPLIT + k0 + tx;
        base[0]    = hi;
        base[1024] = hi;
        base[2048] = lo;
    }
}

// ---------------- 3) column bias from beta -------------------------------------
__global__ void colbias_kernel(const float* __restrict__ w, const float* __restrict__ beta) {
    int c = blockIdx.x*256 + threadIdx.x;
    float s = 0.f;
    for (int k = 0; k < Dm; k++) s += beta[k]*w[(size_t)k*K3 + c];
    g_cbias[c] = s;
}

// ---------------- 4) mma.sync bf16 QKV GEMM + activation epilogue --------------
// C[32768,3072] = A2 @ Wt^T. CTA tile 128x128x32, 8 warps (2x4), warp 64x32.
#define BK   32
#define NKT  (KSPLIT/BK)     // 96
#define LDS_PAD 40           // row stride in bf16 elems (80 bytes)

__device__ __forceinline__ uint32_t smem_u32(const void* p) {
    uint32_t a;
    asm("{ .reg .u64 t; cvta.to.shared.u64 t, %1; cvt.u32.u64 %0, t; }" : "=r"(a) : "l"(p));
    return a;
}
__device__ __forceinline__ void cp16(uint32_t s, const void* g) {
    asm volatile("cp.async.cg.shared.global [%0], [%1], 16;" :: "r"(s), "l"(g));
}
__device__ __forceinline__ void ldmatrix_x4(uint32_t* r, uint32_t a) {
    asm volatile("ldmatrix.sync.aligned.m8n8.x4.shared.b16 {%0,%1,%2,%3}, [%4];"
                 : "=r"(r[0]), "=r"(r[1]), "=r"(r[2]), "=r"(r[3]) : "r"(a));
}
__device__ __forceinline__ void mma16816(float* d, const uint32_t* a, const uint32_t* b) {
    asm volatile("mma.sync.aligned.m16n8k16.row.col.f32.bf16.bf16.f32 "
                 "{%0,%1,%2,%3}, {%4,%5,%6,%7}, {%8,%9}, {%0,%1,%2,%3};"
                 : "+f"(d[0]), "+f"(d[1]), "+f"(d[2]), "+f"(d[3])
                 : "r"(a[0]), "r"(a[1]), "r"(a[2]), "r"(a[3]), "r"(b[0]), "r"(b[1]));
}

__global__ void __launch_bounds__(256,2) qkv_mma_kernel() {
    __shared__ __align__(16) __nv_bfloat16 As[2][128*LDS_PAD];
    __shared__ __align__(16) __nv_bfloat16 Bs[2][128*LDS_PAD];
    const int tid = threadIdx.x;
    const int bn  = blockIdx.x;     // 0..23 column tile
    const int bm  = blockIdx.y;     // 0..255 row tile
    const int m0  = bm*128;

    const __nv_bfloat16* Ag = g_a2 + (size_t)m0*KSPLIT;
    const __nv_bfloat16* Bg = g_wt + (size_t)(bn*128)*KSPLIT;

    const uint32_t a_s0 = smem_u32(&As[0][0]);
    const uint32_t b_s0 = smem_u32(&Bs[0][0]);
    const uint32_t bufB = 128*LDS_PAD*2;      // bytes per buffer

    // prefetch thread mapping: 2 A-chunks + 2 B-chunks of 16B per thread
    const int prow = tid>>2;                  // 0..63
    const int pcol = (tid&3)*8;               // elem col 0,8,16,24
    const uint32_t poff = (uint32_t)(prow*LDS_PAD + pcol)*2;
    const uint32_t poff2 = poff + 64*LDS_PAD*2;

    #define PREFETCH(kt, buf) do {                                              \
        const __nv_bfloat16* gA = Ag + (size_t)prow*KSPLIT + (kt)*BK + pcol;    \
        const __nv_bfloat16* gB = Bg + (size_t)prow*KSPLIT + (kt)*BK + pcol;    \
        uint32_t sa = a_s0 + (buf)*bufB;                                        \
        uint32_t sb = b_s0 + (buf)*bufB;                                        \
        cp16(sa+poff,  gA);                                                     \
        cp16(sa+poff2, gA + (size_t)64*KSPLIT);                                 \
        cp16(sb+poff,  gB);                                                     \
        cp16(sb+poff2, gB + (size_t)64*KSPLIT);                                 \
    } while(0)

    const int w  = tid>>5, lane = tid&31;
    const int wm = w>>2, wn = w&3;
    const int M0 = wm*64, N0 = wn*32;

    // ldmatrix lane address offsets
    const int a_m = (lane&7) + ((lane>>3)&1)*8;   // row within m16
    const int a_k = (lane>>4)*8;                  // col within k16
    const int b_n = (lane&7) + (lane>>4)*8;       // row within n16
    const int b_k = ((lane>>3)&1)*8;              // col within k16

    float acc[4][4][4];
    #pragma unroll
    for (int i=0;i<4;i++)
        #pragma unroll
        for (int j=0;j<4;j++)
            #pragma unroll
            for (int r=0;r<4;r++) acc[i][j][r]=0.f;

    PREFETCH(0, 0);
    asm volatile("cp.async.commit_group;" ::: "memory");

    #pragma unroll 1
    for (int kt = 0; kt < NKT; kt++) {
        const int buf = kt & 1;
        if (kt+1 < NKT) {
            PREFETCH(kt+1, buf^1);
            asm volatile("cp.async.commit_group;" ::: "memory");
            asm volatile("cp.async.wait_group 1;" ::: "memory");
        } else {
            asm volatile("cp.async.wait_group 0;" ::: "memory");
        }
        __syncthreads();

        const uint32_t sa = a_s0 + buf*bufB;
        const uint32_t sb = b_s0 + buf*bufB;
        #pragma unroll
        for (int ks = 0; ks < 2; ks++) {
            const int kk = ks*16;
            uint32_t afr[4][4];
            #pragma unroll
            for (int mt=0;mt<4;mt++)
                ldmatrix_x4(afr[mt], sa + (uint32_t)((M0 + mt*16 + a_m)*LDS_PAD + kk + a_k)*2);
            uint32_t bfr[2][4];
            #pragma unroll
            for (int nh=0;nh<2;nh++)
                ldmatrix_x4(bfr[nh], sb + (uint32_t)((N0 + nh*16 + b_n)*LDS_PAD + kk + b_k)*2);
            #pragma unroll
            for (int mt=0;mt<4;mt++)
                #pragma unroll
                for (int nt=0;nt<4;nt++)
                    mma16816(acc[mt][nt], afr[mt], &bfr[nt>>1][(nt&1)*2]);
        }
        __syncthreads();
    }

    // ---------------- epilogue: bias + activation + scatter ----------------
    const int which = bn >> 3;       // 0=q 1=k 2=v
    const int h     = bn & 7;
    const int b     = m0 >> 13;
    float* dst = (which==0) ? g_q : (which==1) ? g_k : g_v;
    const int qrow = lane>>2;        // 0..7
    const int qcol = (lane&3)*2;     // 0,2,4,6

    #pragma unroll
    for (int mt=0; mt<4; mt++) {
        #pragma unroll
        for (int r2=0; r2<2; r2++) {
            const int n_g = (m0 & (Nseq-1)) + M0 + mt*16 + qrow + r2*8;
            float mfac = 1.f;
            if (which==1) mfac = g_mask[(size_t)b*Nseq + n_g] ? 0.f : 1.f;
            float* prow_p = dst + ((size_t)(b*Hh+h)*Nseq + n_g)*HDim;
            #pragma unroll
            for (int nt=0; nt<4; nt++) {
                const int e = N0 + nt*8 + qcol;
                float v0 = acc[mt][nt][r2*2+0] + g_cbias[bn*128 + e];
                float v1 = acc[mt][nt][r2*2+1] + g_cbias[bn*128 + e + 1];
                if (which==0) {
                    v0 = 1.f/(1.f + __expf(-v0));
                    v1 = 1.f/(1.f + __expf(-v1));
                } else if (which==1) {
                    v0 = tanhf(v0)*mfac;
                    v1 = tanhf(v1)*mfac;
                }
                float2 o{v0, v1};
                *(float2*)(prow_p + e) = o;
            }
        }
    }
    #undef PREFETCH
}

// ---------------- 5) kv partials: per (bh, chunk) 128x128 = k^T v --------------
__global__ void __launch_bounds__(256,2) kv_partial_kernel() {
    const int ch = blockIdx.x;
    const int bh = blockIdx.y;
    __shared__ float Ks[8][128], Vs[8][128];
    const int tid = threadIdx.x;
    const int lr = tid>>5, lc = (tid&31)*4;
    const size_t base = ((size_t)bh*Nseq + ch*256)*HDim + (size_t)lr*HDim + lc;
    const float* kp = g_k + base;
    const float* vp = g_v + base;

    float acc[8][8];
    #pragma unroll
    for (int i=0;i<8;i++)
        #pragma unroll
        for (int j=0;j<8;j++) acc[i][j]=0.f;
    const int ty = tid>>4, tx = tid&15;

    for (int s = 0; s < 32; s++) {
        *(float4*)&Ks[lr][lc] = *(const float4*)(kp + (size_t)s*8*HDim);
        *(float4*)&Vs[lr][lc] = *(const float4*)(vp + (size_t)s*8*HDim);
        __syncthreads();
        #pragma unroll
        for (int kk=0; kk<8; kk++){
            float ar[8], br[8];
            *(float4*)&ar[0] = *(const float4*)&Ks[kk][ty*8];
            *(float4*)&ar[4] = *(const float4*)&Ks[kk][ty*8+4];
            *(float4*)&br[0] = *(const float4*)&Vs[kk][tx*8];
            *(float4*)&br[4] = *(const float4*)&Vs[kk][tx*8+4];
            #pragma unroll
            for (int i=0;i<8;i++)
                #pragma unroll
                for (int j=0;j<8;j++)
                    acc[i][j] = fmaf(ar[i], br[j], acc[i][j]);
        }
        __syncthreads();
    }
    float* p = g_kvp + (size_t)(bh*NCHUNK + ch)*HDim*HDim;
    #pragma unroll
    for (int i=0;i<8;i++){
        float* pp = p + (size_t)(ty*8+i)*HDim + tx*8;
        *(float4*)pp     = *(float4*)&acc[i][0];
        *(float4*)(pp+4) = *(float4*)&acc[i][4];
    }
}

// ---------------- 6) deterministic reduce of kv partials -----------------------
__global__ void kv_reduce_kernel() {
    int bh  = blockIdx.y;
    int idx = blockIdx.x*256 + threadIdx.x;
    float s = 0.f;
    #pragma unroll
    for (int c = 0; c < NCHUNK; c++)
        s += g_kvp[(size_t)(bh*NCHUNK + c)*HDim*HDim + idx];
    g_kv[(size_t)bh*HDim*HDim + idx] = s;
}

// ---------------- 7) out = q @ kv, scatter to [B,N,D] --------------------------
__global__ void __launch_bounds__(256,2) out_kernel(float* __restrict__ out) {
    const int mt = blockIdx.x;
    const int bh = blockIdx.y;
    const int b = bh>>3, h = bh&7;
    __shared__ float As2[8][128], Bs2[8][128];
    const int tid = threadIdx.x;
    const int arow = tid>>1,  acol = (tid&1)*4;
    const int brow = tid>>5,  bcol = (tid&31)*4;
    const float* Ap = g_q  + ((size_t)bh*Nseq + mt*128 + arow)*HDim + acol;
    const float* Bp = g_kv + (size_t)bh*HDim*HDim + (size_t)brow*HDim + bcol;

    float acc[8][8];
    #pragma unroll
    for (int i=0;i<8;i++)
        #pragma unroll
        for (int j=0;j<8;j++) acc[i][j]=0.f;
    const int ty = tid>>4, tx = tid&15;

    for (int kt = 0; kt < HDim/8; kt++) {
        float4 av = *(const float4*)(Ap + kt*8);
        As2[acol+0][arow]=av.x; As2[acol+1][arow]=av.y;
        As2[acol+2][arow]=av.z; As2[acol+3][arow]=av.w;
        *(float4*)&Bs2[brow][bcol] = *(const float4*)(Bp + (size_t)kt*8*HDim);
        __syncthreads();
        #pragma unroll
        for (int kk=0; kk<8; kk++){
            float ar[8], br[8];
            *(float4*)&ar[0] = *(const float4*)&As2[kk][ty*8];
            *(float4*)&ar[4] = *(const float4*)&As2[kk][ty*8+4];
            *(float4*)&br[0] = *(const float4*)&Bs2[kk][tx*8];
            *(float4*)&br[4] = *(const float4*)&Bs2[kk][tx*8+4];
            #pragma unroll
            for (int i=0;i<8;i++)
                #pragma unroll
                for (int j=0;j<8;j++)
                    acc[i][j] = fmaf(ar[i], br[j], acc[i][j]);
        }
        __syncthreads();
    }

    #pragma unroll
    for (int i=0;i<8;i++){
        int n = mt*128 + ty*8 + i;
        float* p = out + ((size_t)b*Nseq + n)*Dm + h*HDim + tx*8;
        *(float4*)p     = *(float4*)&acc[i][0];
        *(float4*)(p+4) = *(float4*)&acc[i][4];
    }
}

// ---------------- launch --------------------------------------------------------
extern "C" void kernel_launch(void* const* d_in, const int* in_sizes, int n_in,
                              void* d_out, int out_size) {
    const float* x = 0; const void* mask = 0; const float* w = 0;
    const float* gamma = 0; const float* beta = 0;
    for (int i = 0; i < n_in; i++) {
        int s = in_sizes[i];
        if      (s == 33554432) x    = (const float*)d_in[i];
        else if (s == 32768)    mask = d_in[i];
        else if (s == 3145728)  w    = (const float*)d_in[i];
        else if (s == 1024)     { if (!gamma) gamma = (const float*)d_in[i];
                                  else        beta  = (const float*)d_in[i]; }
    }
    float* out = (float*)d_out;

    mask_reset_kernel<<<1, 1>>>();
    mask_probe_kernel<<<32, 256>>>((const unsigned int*)mask);
    mask_norm_kernel<<<128, 256>>>(mask);
    ln_a2_kernel<<<Mrows, 256>>>(x);
    build_wt_kernel<<<dim3(K3/32, Dm/32), 256>>>(w, gamma);
    colbias_kernel<<<K3/256, 256>>>(w, beta);
    qkv_mma_kernel<<<dim3(24, 256), 256>>>();
    kv_partial_kernel<<<dim3(NCHUNK, BH), 256>>>();
    kv_reduce_kernel<<<dim3(64, BH), 256>>>();
    out_kernel<<<dim3(64, BH), 256>>>(out);
}

// round 6
// speedup vs baseline: 2.2562x; 1.1666x over previous
#include <cuda_runtime.h>
#include <cuda_bf16.h>
#include <cstdint>
#include <math.h>

// Problem constants
#define Bsz  4
#define Nseq 8192
#define Dm   1024
#define Hh   8
#define HDim 128
#define BH   (Bsz*Hh)        // 32
#define Mrows (Bsz*Nseq)     // 32768
#define K3   (3*Dm)          // 3072 output cols
#define KA   2048            // A split contraction storage (hi|lo)
#define NCH2 16              // kv n-chunks

// ---------------- scratch (static device globals; no allocations) -------------
__device__ __nv_bfloat16 g_a2[(size_t)Mrows*KA];      // 128 MiB [hi|lo]
__device__ __nv_bfloat16 g_wt[(size_t)K3*K3];         // 18 MiB per col: [w_hi|w_hi|w_lo]
__device__ float g_cbias[K3];
__device__ __nv_bfloat16 g_qhi[(size_t)BH*Nseq*HDim]; // [bh][n][d]
__device__ __nv_bfloat16 g_qlo[(size_t)BH*Nseq*HDim];
__device__ __nv_bfloat16 g_kth[(size_t)BH*HDim*Nseq]; // [bh][d][n] transposed
__device__ __nv_bfloat16 g_ktl[(size_t)BH*HDim*Nseq];
__device__ __nv_bfloat16 g_vth[(size_t)BH*HDim*Nseq];
__device__ __nv_bfloat16 g_vtl[(size_t)BH*HDim*Nseq];
__device__ float g_kvp[(size_t)BH*NCH2*HDim*HDim];    // 33.5 MiB partials
__device__ __nv_bfloat16 g_kvt2[(size_t)BH*HDim*384]; // [bh][e][hi|hi|lo over d]
__device__ unsigned char g_mask[Bsz*Nseq];

// ---------------- 1) fused mask probe + normalize (single block) --------------
__global__ void mask_all_kernel(const unsigned int* __restrict__ m) {
    __shared__ unsigned int flag;
    if (threadIdx.x == 0) flag = 0u;
    __syncthreads();
    unsigned int loc = 0;
    #pragma unroll
    for (int i = threadIdx.x; i < 8192; i += 1024) loc |= (m[i] > 1u);
    if (loc) atomicOr(&flag, 1u);
    __syncthreads();
    const bool bytelay = (flag != 0u);
    for (int i = threadIdx.x; i < Bsz*Nseq; i += 1024)
        g_mask[i] = bytelay ? (((const unsigned char*)m)[i] ? 1 : 0)
                            : (((const int*)m)[i]           ? 1 : 0);
}

// ---------------- 2) fused LN stats + A2 (bf16 hi/lo) build -------------------
__global__ void ln_a2_kernel(const float* __restrict__ x) {
    int row = blockIdx.x;
    float4 v = reinterpret_cast<const float4*>(x)[(size_t)row*(Dm/4) + threadIdx.x];
    float s  = v.x+v.y+v.z+v.w;
    float ss = v.x*v.x+v.y*v.y+v.z*v.z+v.w*v.w;
    __shared__ float sh[8], sh2[8];
    __shared__ float s_mu, s_rs;
    #pragma unroll
    for (int o=16;o;o>>=1){ s+=__shfl_down_sync(~0u,s,o); ss+=__shfl_down_sync(~0u,ss,o); }
    int w = threadIdx.x>>5, l = threadIdx.x&31;
    if (l==0){ sh[w]=s; sh2[w]=ss; }
    __syncthreads();
    if (threadIdx.x < 8) {
        s = sh[threadIdx.x]; ss = sh2[threadIdx.x];
        #pragma unroll
        for (int o=4;o;o>>=1){ s+=__shfl_down_sync(0xffu,s,o); ss+=__shfl_down_sync(0xffu,ss,o); }
        if (threadIdx.x==0){
            float m = s*(1.0f/Dm);
            float var = ss*(1.0f/Dm) - m*m;
            s_mu = m; s_rs = rsqrtf(var + 1e-5f);
        }
    }
    __syncthreads();
    float mu = s_mu, rs = s_rs;
    float n0=(v.x-mu)*rs, n1=(v.y-mu)*rs, n2=(v.z-mu)*rs, n3=(v.w-mu)*rs;
    __nv_bfloat16 h0=__float2bfloat16(n0), h1=__float2bfloat16(n1),
                  h2=__float2bfloat16(n2), h3=__float2bfloat16(n3);
    __nv_bfloat16 l0=__float2bfloat16(n0-__bfloat162float(h0)),
                  l1=__float2bfloat16(n1-__bfloat162float(h1)),
                  l2=__float2bfloat16(n2-__bfloat162float(h2)),
                  l3=__float2bfloat16(n3-__bfloat162float(h3));
    __nv_bfloat162 hp0{h0,h1}, hp1{h2,h3}, lp0{l0,l1}, lp1{l2,l3};
    uint2 hw{*(uint32_t*)&hp0, *(uint32_t*)&hp1};
    uint2 lw{*(uint32_t*)&lp0, *(uint32_t*)&lp1};
    __nv_bfloat16* base = g_a2 + (size_t)row*KA;
    ((uint2*)base)[threadIdx.x]          = hw;   // k in [0,1024):    hi
    ((uint2*)(base + 1024))[threadIdx.x] = lw;   // k in [1024,2048): lo
}

// ---------------- 3) Wt build + colbias (fused, deterministic) ----------------
// One CTA owns 32 n-columns across ALL k -> exact cbias, no atomics.
__global__ void __launch_bounds__(256) build_wt_cb_kernel(
    const float* __restrict__ w, const float* __restrict__ gamma,
    const float* __restrict__ beta)
{
    __shared__ float tile[32][33];
    __shared__ float cbpart[8][32];
    const int n0 = blockIdx.x*32;
    const int tx = threadIdx.x & 31, ty = threadIdx.x >> 5;
    float cb = 0.f;
    for (int k0 = 0; k0 < Dm; k0 += 32) {
        #pragma unroll
        for (int r=0;r<4;r++){
            int kk = ty + r*8;
            float raw = w[(size_t)(k0+kk)*K3 + n0 + tx];
            cb += beta[k0+kk]*raw;
            tile[kk][tx] = raw * gamma[k0+kk];
        }
        __syncthreads();
        #pragma unroll
        for (int r=0;r<4;r++){
            int nn = ty + r*8;
            float val = tile[tx][nn];
            __nv_bfloat16 hi = __float2bfloat16(val);
            __nv_bfloat16 lo = __float2bfloat16(val - __bfloat162float(hi));
            __nv_bfloat16* base = g_wt + (size_t)(n0+nn)*K3 + k0 + tx;
            base[0]    = hi;
            base[1024] = hi;
            base[2048] = lo;
        }
        __syncthreads();
    }
    cbpart[ty][tx] = cb;
    __syncthreads();
    if (ty == 0) {
        float s = 0.f;
        #pragma unroll
        for (int r=0;r<8;r++) s += cbpart[r][tx];
        g_cbias[n0+tx] = s;
    }
}

// ================= mma.sync building blocks (validated in R4) ==================
#define LDS_PAD 40           // row stride in bf16 elems (80 bytes)
#define STAGE_B 20480        // bytes per pipeline stage (A 10240 + B 10240)

__device__ __forceinline__ uint32_t smem_u32(const void* p) {
    uint32_t a;
    asm("{ .reg .u64 t; cvta.to.shared.u64 t, %1; cvt.u32.u64 %0, t; }" : "=r"(a) : "l"(p));
    return a;
}
__device__ __forceinline__ void cp16(uint32_t s, const void* g) {
    asm volatile("cp.async.cg.shared.global [%0], [%1], 16;" :: "r"(s), "l"(g));
}
__device__ __forceinline__ void cp_commit() {
    asm volatile("cp.async.commit_group;" ::: "memory");
}
__device__ __forceinline__ void ldmatrix_x4(uint32_t* r, uint32_t a) {
    asm volatile("ldmatrix.sync.aligned.m8n8.x4.shared.b16 {%0,%1,%2,%3}, [%4];"
                 : "=r"(r[0]), "=r"(r[1]), "=r"(r[2]), "=r"(r[3]) : "r"(a));
}
__device__ __forceinline__ void mma16816(float* d, const uint32_t* a, const uint32_t* b) {
    asm volatile("mma.sync.aligned.m16n8k16.row.col.f32.bf16.bf16.f32 "
                 "{%0,%1,%2,%3}, {%4,%5,%6,%7}, {%8,%9}, {%0,%1,%2,%3};"
                 : "+f"(d[0]), "+f"(d[1]), "+f"(d[2]), "+f"(d[3])
                 : "r"(a[0]), "r"(a[1]), "r"(a[2]), "r"(a[3]), "r"(b[0]), "r"(b[1]));
}

// Compute one BK=32 step from stage smem (sa,sb); warp tile 64x32 (2x4 warps).
#define MMA_STEP(sa, sb)                                                          \
    do {                                                                          \
        _Pragma("unroll")                                                         \
        for (int ks = 0; ks < 2; ks++) {                                          \
            const int kk = ks*16;                                                 \
            uint32_t afr[4][4];                                                   \
            _Pragma("unroll")                                                     \
            for (int mt=0;mt<4;mt++)                                              \
                ldmatrix_x4(afr[mt], (sa) + (uint32_t)((M0 + mt*16 + a_m)*LDS_PAD + kk + a_k)*2); \
            uint32_t bfr[2][4];                                                   \
            _Pragma("unroll")                                                     \
            for (int nh=0;nh<2;nh++)                                              \
                ldmatrix_x4(bfr[nh], (sb) + (uint32_t)((N0 + nh*16 + b_n)*LDS_PAD + kk + b_k)*2); \
            _Pragma("unroll")                                                     \
            for (int mt=0;mt<4;mt++)                                              \
                _Pragma("unroll")                                                 \
                for (int nt=0;nt<4;nt++)                                          \
                    mma16816(acc[mt][nt], afr[mt], &bfr[nt>>1][(nt&1)*2]);        \
        }                                                                         \
    } while (0)

#define WARP_VARS                                                                 \
    const int w  = tid>>5, lane = tid&31;                                         \
    const int wm = w>>2, wn = w&3;                                                \
    const int M0 = wm*64, N0 = wn*32;                                             \
    const int a_m = (lane&7) + ((lane>>3)&1)*8;                                   \
    const int a_k = (lane>>4)*8;                                                  \
    const int b_n = (lane&7) + (lane>>4)*8;                                       \
    const int b_k = ((lane>>3)&1)*8;                                              \
    float acc[4][4][4];                                                           \
    _Pragma("unroll")                                                             \
    for (int i=0;i<4;i++)                                                         \
        _Pragma("unroll")                                                         \
        for (int j=0;j<4;j++)                                                     \
            _Pragma("unroll")                                                     \
            for (int r=0;r<4;r++) acc[i][j][r]=0.f;

// ---------------- 4) QKV GEMM: C = A2 @ Wt^T, 4-stage pipeline ----------------
// K mapping: wt k = kt*32 in [hi|hi|lo]; a2 k = (kt&63)*32 in [hi|lo].
__global__ void __launch_bounds__(256,2) qkv_mma_kernel() {
    extern __shared__ char smdyn[];
    const int tid = threadIdx.x;
    const int bn  = blockIdx.x;     // 0..23
    const int bm  = blockIdx.y;     // 0..255
    const int m0  = bm*128;
    const __nv_bfloat16* Ag = g_a2 + (size_t)m0*KA;
    const __nv_bfloat16* Bg = g_wt + (size_t)(bn*128)*K3;
    const uint32_t sbase = smem_u32(smdyn);
    const int prow = tid>>2;
    const int pcol = (tid&3)*8;
    const uint32_t poff  = (uint32_t)(prow*LDS_PAD + pcol)*2;
    const uint32_t poff2 = poff + 64*LDS_PAD*2;

    #define QKV_PF(kt) do {                                                       \
        uint32_t sa = sbase + ((kt)&3)*STAGE_B, sb = sa + 10240;                  \
        const __nv_bfloat16* gA = Ag + (size_t)prow*KA + ((kt)&63)*32 + pcol;     \
        const __nv_bfloat16* gB = Bg + (size_t)prow*K3 + (kt)*32 + pcol;          \
        cp16(sa+poff,  gA); cp16(sa+poff2, gA + (size_t)64*KA);                   \
        cp16(sb+poff,  gB); cp16(sb+poff2, gB + (size_t)64*K3);                   \
    } while(0)

    WARP_VARS;
    QKV_PF(0); cp_commit(); QKV_PF(1); cp_commit(); QKV_PF(2); cp_commit();

    #pragma unroll 1
    for (int kt = 0; kt < 96; kt++) {
        asm volatile("cp.async.wait_group 2;" ::: "memory");
        __syncthreads();
        if (kt+3 < 96) QKV_PF(kt+3);
        cp_commit();
        const uint32_t sa = sbase + (kt&3)*STAGE_B, sb = sa + 10240;
        MMA_STEP(sa, sb);
    }
    #undef QKV_PF

    // epilogue: bias + activation + hi/lo emit (q natural, k/v transposed)
    const int which = bn >> 3;       // 0=q 1=k 2=v
    const int h     = bn & 7;
    const int b     = m0 >> 13;
    const int bh    = b*Hh + h;
    const int qrow  = lane>>2;
    const int qcol  = (lane&3)*2;

    #pragma unroll
    for (int mt=0; mt<4; mt++) {
        #pragma unroll
        for (int r2=0; r2<2; r2++) {
            const int n_g = (m0 & (Nseq-1)) + M0 + mt*16 + qrow + r2*8;
            float mfac = 1.f;
            if (which==1) mfac = g_mask[(size_t)b*Nseq + n_g] ? 0.f : 1.f;
            #pragma unroll
            for (int nt=0; nt<4; nt++) {
                const int e = N0 + nt*8 + qcol;
                float v0 = acc[mt][nt][r2*2+0] + g_cbias[bn*128 + e];
                float v1 = acc[mt][nt][r2*2+1] + g_cbias[bn*128 + e + 1];
                if (which==0) {
                    v0 = 1.f/(1.f + __expf(-v0));
                    v1 = 1.f/(1.f + __expf(-v1));
                } else if (which==1) {
                    v0 = tanhf(v0)*mfac;
                    v1 = tanhf(v1)*mfac;
                }
                __nv_bfloat16 h0=__float2bfloat16(v0), h1=__float2bfloat16(v1);
                __nv_bfloat16 q0=__float2bfloat16(v0-__bfloat162float(h0)),
                              q1=__float2bfloat16(v1-__bfloat162float(h1));
                if (which==0) {
                    __nv_bfloat162 hp{h0,h1}, lp{q0,q1};
                    size_t idx = ((size_t)bh*Nseq + n_g)*HDim + e;
                    *(uint32_t*)&g_qhi[idx] = *(uint32_t*)&hp;
                    *(uint32_t*)&g_qlo[idx] = *(uint32_t*)&lp;
                } else {
                    __nv_bfloat16* dh = (which==1) ? g_kth : g_vth;
                    __nv_bfloat16* dl = (which==1) ? g_ktl : g_vtl;
                    size_t i0 = ((size_t)bh*HDim + e)*Nseq + n_g;
                    dh[i0] = h0; dh[i0 + Nseq] = h1;
                    dl[i0] = q0; dl[i0 + Nseq] = q1;
                }
            }
        }
    }
}

// ---------------- 5) kv partials via mma: kv = k^T v (3-term bf16 split) ------
// A = kt[d][n], B = vt[e][n]; contraction over n. Segments: hh, lh, hl.
__global__ void __launch_bounds__(256,2) kv_mma_kernel() {
    extern __shared__ char smdyn[];
    const int tid = threadIdx.x;
    const int ch  = blockIdx.x;     // 0..15 (n-slice of 512)
    const int bh  = blockIdx.y;     // 0..31
    const size_t obh = (size_t)bh*HDim*Nseq;
    const __nv_bfloat16* Aseg[3] = { g_kth+obh, g_ktl+obh, g_kth+obh };
    const __nv_bfloat16* Bseg[3] = { g_vth+obh, g_vth+obh, g_vtl+obh };
    const uint32_t sbase = smem_u32(smdyn);
    const int prow = tid>>2;
    const int pcol = (tid&3)*8;
    const uint32_t poff  = (uint32_t)(prow*LDS_PAD + pcol)*2;
    const uint32_t poff2 = poff + 64*LDS_PAD*2;

    #define KV_PF(kt) do {                                                        \
        uint32_t sa = sbase + ((kt)&3)*STAGE_B, sb = sa + 10240;                  \
        const int seg = (kt)>>4;                                                  \
        const int nc  = ch*512 + ((kt)&15)*32 + pcol;                             \
        const __nv_bfloat16* gA = Aseg[seg] + (size_t)prow*Nseq + nc;             \
        const __nv_bfloat16* gB = Bseg[seg] + (size_t)prow*Nseq + nc;             \
        cp16(sa+poff,  gA); cp16(sa+poff2, gA + (size_t)64*Nseq);                 \
        cp16(sb+poff,  gB); cp16(sb+poff2, gB + (size_t)64*Nseq);                 \
    } while(0)

    WARP_VARS;
    KV_PF(0); cp_commit(); KV_PF(1); cp_commit(); KV_PF(2); cp_commit();

    #pragma unroll 1
    for (int kt = 0; kt < 48; kt++) {
        asm volatile("cp.async.wait_group 2;" ::: "memory");
        __syncthreads();
        if (kt+3 < 48) KV_PF(kt+3);
        cp_commit();
        const uint32_t sa = sbase + (kt&3)*STAGE_B, sb = sa + 10240;
        MMA_STEP(sa, sb);
    }
    #undef KV_PF

    const int qrow = lane>>2, qcol = (lane&3)*2;
    float* p = g_kvp + ((size_t)(bh*NCH2 + ch) << 14);
    #pragma unroll
    for (int mt=0; mt<4; mt++)
        #pragma unroll
        for (int r2=0; r2<2; r2++) {
            const int d = M0 + mt*16 + qrow + r2*8;
            #pragma unroll
            for (int nt=0; nt<4; nt++) {
                const int e = N0 + nt*8 + qcol;
                float2 o{acc[mt][nt][r2*2+0], acc[mt][nt][r2*2+1]};
                *(float2*)(p + (size_t)d*HDim + e) = o;
            }
        }
}

// ---------------- 6) reduce partials -> kvt2 [bh][e][hi|hi|lo over d] ---------
__global__ void kv_reduce_kernel() {
    const int bh  = blockIdx.y;
    const int idx = blockIdx.x*256 + threadIdx.x;   // grid.x=64 -> 16384
    float s = 0.f;
    #pragma unroll
    for (int c = 0; c < NCH2; c++)
        s += g_kvp[((size_t)(bh*NCH2 + c) << 14) + idx];
    const int d = idx >> 7, e = idx & 127;
    __nv_bfloat16 hi = __float2bfloat16(s);
    __nv_bfloat16 lo = __float2bfloat16(s - __bfloat162float(hi));
    __nv_bfloat16* base = g_kvt2 + ((size_t)bh*HDim + e)*384 + d;
    base[0]   = hi;
    base[128] = hi;
    base[256] = lo;
}

// ---------------- 7) out = q @ kv via mma (K=384), scatter fp32 ---------------
__global__ void __launch_bounds__(256,2) out_mma_kernel(float* __restrict__ out) {
    extern __shared__ char smdyn[];
    const int tid = threadIdx.x;
    const int mt0 = blockIdx.x;     // 0..63
    const int bh  = blockIdx.y;     // 0..31
    const int m0  = mt0*128;
    const size_t oq = ((size_t)bh*Nseq + m0)*HDim;
    const __nv_bfloat16* Aseg[3] = { g_qhi+oq, g_qlo+oq, g_qhi+oq };
    const __nv_bfloat16* Bg = g_kvt2 + (size_t)bh*HDim*384;
    const uint32_t sbase = smem_u32(smdyn);
    const int prow = tid>>2;
    const int pcol = (tid&3)*8;
    const uint32_t poff  = (uint32_t)(prow*LDS_PAD + pcol)*2;
    const uint32_t poff2 = poff + 64*LDS_PAD*2;

    #define OUT_PF(kt) do {                                                       \
        uint32_t sa = sbase + ((kt)&3)*STAGE_B, sb = sa + 10240;                  \
        const int seg = (kt)>>2;                                                  \
        const __nv_bfloat16* gA = Aseg[seg] + (size_t)prow*HDim + ((kt)&3)*32 + pcol; \
        const __nv_bfloat16* gB = Bg + (size_t)prow*384 + (kt)*32 + pcol;         \
        cp16(sa+poff,  gA); cp16(sa+poff2, gA + (size_t)64*HDim);                 \
        cp16(sb+poff,  gB); cp16(sb+poff2, gB + (size_t)64*384);                  \
    } while(0)

    WARP_VARS;
    OUT_PF(0); cp_commit(); OUT_PF(1); cp_commit(); OUT_PF(2); cp_commit();

    #pragma unroll 1
    for (int kt = 0; kt < 12; kt++) {
        asm volatile("cp.async.wait_group 2;" ::: "memory");
        __syncthreads();
        if (kt+3 < 12) OUT_PF(kt+3);
        cp_commit();
        const uint32_t sa = sbase + (kt&3)*STAGE_B, sb = sa + 10240;
        MMA_STEP(sa, sb);
    }
    #undef OUT_PF

    const int b = bh>>3, h = bh&7;
    const int qrow = lane>>2, qcol = (lane&3)*2;
    #pragma unroll
    for (int mt=0; mt<4; mt++)
        #pragma unroll
        for (int r2=0; r2<2; r2++) {
            const int n_g = m0 + M0 + mt*16 + qrow + r2*8;
            float* prow_p = out + ((size_t)b*Nseq + n_g)*Dm + h*HDim;
            #pragma unroll
            for (int nt=0; nt<4; nt++) {
                const int e = N0 + nt*8 + qcol;
                float2 o{acc[mt][nt][r2*2+0], acc[mt][nt][r2*2+1]};
                *(float2*)(prow_p + e) = o;
            }
        }
}

// ---------------- launch --------------------------------------------------------
extern "C" void kernel_launch(void* const* d_in, const int* in_sizes, int n_in,
                              void* d_out, int out_size) {
    const float* x = 0; const void* mask = 0; const float* w = 0;
    const float* gamma = 0; const float* beta = 0;
    for (int i = 0; i < n_in; i++) {
        int s = in_sizes[i];
        if      (s == 33554432) x    = (const float*)d_in[i];
        else if (s == 32768)    mask = d_in[i];
        else if (s == 3145728)  w    = (const float*)d_in[i];
        else if (s == 1024)     { if (!gamma) gamma = (const float*)d_in[i];
                                  else        beta  = (const float*)d_in[i]; }
    }
    float* out = (float*)d_out;

    const int smbytes = 4*STAGE_B;   // 81920
    cudaFuncSetAttribute(qkv_mma_kernel, cudaFuncAttributeMaxDynamicSharedMemorySize, smbytes);
    cudaFuncSetAttribute(kv_mma_kernel,  cudaFuncAttributeMaxDynamicSharedMemorySize, smbytes);
    cudaFuncSetAttribute(out_mma_kernel, cudaFuncAttributeMaxDynamicSharedMemorySize, smbytes);

    mask_all_kernel<<<1, 1024>>>((const unsigned int*)mask);            // 1
    ln_a2_kernel<<<Mrows, 256>>>(x);                                    // 2
    build_wt_cb_kernel<<<K3/32, 256>>>(w, gamma, beta);                 // 3
    qkv_mma_kernel<<<dim3(24, 256), 256, smbytes>>>();                  // 4 (profiled)
    kv_mma_kernel<<<dim3(NCH2, BH), 256, smbytes>>>();                  // 5
    kv_reduce_kernel<<<dim3(64, BH), 256>>>();                          // 6
    out_mma_kernel<<<dim3(64, BH), 256, smbytes>>>(out);                // 7
}

// round 7
// speedup vs baseline: 2.5464x; 1.1286x over previous
#include <cuda_runtime.h>
#include <cuda_bf16.h>
#include <cstdint>
#include <math.h>

// Problem constants
#define Bsz  4
#define Nseq 8192
#define Dm   1024
#define Hh   8
#define HDim 128
#define BH   (Bsz*Hh)        // 32
#define Mrows (Bsz*Nseq)     // 32768
#define K3   (3*Dm)          // 3072 output cols
#define KA   2048            // A split contraction storage (hi|lo)
#define NCH2 16              // kv n-chunks

// ---------------- scratch (static device globals; no allocations) -------------
__device__ __nv_bfloat16 g_a2[(size_t)Mrows*KA];      // 128 MiB [hi|lo]
__device__ __nv_bfloat16 g_wt[(size_t)K3*K3];         // 18 MiB per col: [w_hi|w_hi|w_lo]
__device__ float g_cbias[K3];
__device__ __nv_bfloat16 g_qhi[(size_t)BH*Nseq*HDim]; // [bh][n][d]
__device__ __nv_bfloat16 g_qlo[(size_t)BH*Nseq*HDim];
__device__ __nv_bfloat16 g_kth[(size_t)BH*HDim*Nseq]; // [bh][d][n] transposed
__device__ __nv_bfloat16 g_ktl[(size_t)BH*HDim*Nseq];
__device__ __nv_bfloat16 g_vth[(size_t)BH*HDim*Nseq];
__device__ __nv_bfloat16 g_vtl[(size_t)BH*HDim*Nseq];
__device__ float g_kvp[(size_t)BH*NCH2*HDim*HDim];    // 33.5 MiB partials
__device__ __nv_bfloat16 g_kvt2[(size_t)BH*HDim*384]; // [bh][e][hi|hi|lo over d]
__device__ unsigned char g_mask[Bsz*Nseq];

// ---------------- 1) fused mask probe + normalize (single block) --------------
__global__ void mask_all_kernel(const unsigned int* __restrict__ m) {
    __shared__ unsigned int flag;
    if (threadIdx.x == 0) flag = 0u;
    __syncthreads();
    unsigned int loc = 0;
    #pragma unroll
    for (int i = threadIdx.x; i < 8192; i += 1024) loc |= (m[i] > 1u);
    if (loc) atomicOr(&flag, 1u);
    __syncthreads();
    const bool bytelay = (flag != 0u);
    for (int i = threadIdx.x; i < Bsz*Nseq; i += 1024)
        g_mask[i] = bytelay ? (((const unsigned char*)m)[i] ? 1 : 0)
                            : (((const int*)m)[i]           ? 1 : 0);
}

// ---------------- 2) fused LN stats + A2 (bf16 hi/lo) build -------------------
__global__ void ln_a2_kernel(const float* __restrict__ x) {
    int row = blockIdx.x;
    float4 v = reinterpret_cast<const float4*>(x)[(size_t)row*(Dm/4) + threadIdx.x];
    float s  = v.x+v.y+v.z+v.w;
    float ss = v.x*v.x+v.y*v.y+v.z*v.z+v.w*v.w;
    __shared__ float sh[8], sh2[8];
    __shared__ float s_mu, s_rs;
    #pragma unroll
    for (int o=16;o;o>>=1){ s+=__shfl_down_sync(~0u,s,o); ss+=__shfl_down_sync(~0u,ss,o); }
    int w = threadIdx.x>>5, l = threadIdx.x&31;
    if (l==0){ sh[w]=s; sh2[w]=ss; }
    __syncthreads();
    if (threadIdx.x < 8) {
        s = sh[threadIdx.x]; ss = sh2[threadIdx.x];
        #pragma unroll
        for (int o=4;o;o>>=1){ s+=__shfl_down_sync(0xffu,s,o); ss+=__shfl_down_sync(0xffu,ss,o); }
        if (threadIdx.x==0){
            float m = s*(1.0f/Dm);
            float var = ss*(1.0f/Dm) - m*m;
            s_mu = m; s_rs = rsqrtf(var + 1e-5f);
        }
    }
    __syncthreads();
    float mu = s_mu, rs = s_rs;
    float n0=(v.x-mu)*rs, n1=(v.y-mu)*rs, n2=(v.z-mu)*rs, n3=(v.w-mu)*rs;
    __nv_bfloat16 h0=__float2bfloat16(n0), h1=__float2bfloat16(n1),
                  h2=__float2bfloat16(n2), h3=__float2bfloat16(n3);
    __nv_bfloat16 l0=__float2bfloat16(n0-__bfloat162float(h0)),
                  l1=__float2bfloat16(n1-__bfloat162float(h1)),
                  l2=__float2bfloat16(n2-__bfloat162float(h2)),
                  l3=__float2bfloat16(n3-__bfloat162float(h3));
    __nv_bfloat162 hp0{h0,h1}, hp1{h2,h3}, lp0{l0,l1}, lp1{l2,l3};
    uint2 hw{*(uint32_t*)&hp0, *(uint32_t*)&hp1};
    uint2 lw{*(uint32_t*)&lp0, *(uint32_t*)&lp1};
    __nv_bfloat16* base = g_a2 + (size_t)row*KA;
    ((uint2*)base)[threadIdx.x]          = hw;
    ((uint2*)(base + 1024))[threadIdx.x] = lw;
}

// ---------------- 3) Wt build + colbias (fused, deterministic) ----------------
__global__ void __launch_bounds__(256) build_wt_cb_kernel(
    const float* __restrict__ w, const float* __restrict__ gamma,
    const float* __restrict__ beta)
{
    __shared__ float tile[32][33];
    __shared__ float cbpart[8][32];
    const int n0 = blockIdx.x*32;
    const int tx = threadIdx.x & 31, ty = threadIdx.x >> 5;
    float cb = 0.f;
    for (int k0 = 0; k0 < Dm; k0 += 32) {
        #pragma unroll
        for (int r=0;r<4;r++){
            int kk = ty + r*8;
            float raw = w[(size_t)(k0+kk)*K3 + n0 + tx];
            cb += beta[k0+kk]*raw;
            tile[kk][tx] = raw * gamma[k0+kk];
        }
        __syncthreads();
        #pragma unroll
        for (int r=0;r<4;r++){
            int nn = ty + r*8;
            float val = tile[tx][nn];
            __nv_bfloat16 hi = __float2bfloat16(val);
            __nv_bfloat16 lo = __float2bfloat16(val - __bfloat162float(hi));
            __nv_bfloat16* base = g_wt + (size_t)(n0+nn)*K3 + k0 + tx;
            base[0]    = hi;
            base[1024] = hi;
            base[2048] = lo;
        }
        __syncthreads();
    }
    cbpart[ty][tx] = cb;
    __syncthreads();
    if (ty == 0) {
        float s = 0.f;
        #pragma unroll
        for (int r=0;r<8;r++) s += cbpart[r][tx];
        g_cbias[n0+tx] = s;
    }
}

// ================= mma.sync building blocks ====================================
#define LDS_PAD 72           // row stride in bf16 elems for BK=64 (144B: bank rot 4)
#define TILE_B  18432        // bytes per 128x64 operand tile (128*72*2)
#define STAGE_B 36864        // A + B per stage
#define NSTAGE  3
#define SMEM_SZ (NSTAGE*STAGE_B)   // 110592

__device__ __forceinline__ uint32_t smem_u32(const void* p) {
    uint32_t a;
    asm("{ .reg .u64 t; cvta.to.shared.u64 t, %1; cvt.u32.u64 %0, t; }" : "=r"(a) : "l"(p));
    return a;
}
__device__ __forceinline__ void cp16(uint32_t s, const void* g) {
    asm volatile("cp.async.cg.shared.global [%0], [%1], 16;" :: "r"(s), "l"(g));
}
__device__ __forceinline__ void cp_commit() {
    asm volatile("cp.async.commit_group;" ::: "memory");
}
__device__ __forceinline__ void ldmatrix_x4(uint32_t* r, uint32_t a) {
    asm volatile("ldmatrix.sync.aligned.m8n8.x4.shared.b16 {%0,%1,%2,%3}, [%4];"
                 : "=r"(r[0]), "=r"(r[1]), "=r"(r[2]), "=r"(r[3]) : "r"(a));
}
__device__ __forceinline__ void mma16816(float* d, const uint32_t* a, const uint32_t* b) {
    asm volatile("mma.sync.aligned.m16n8k16.row.col.f32.bf16.bf16.f32 "
                 "{%0,%1,%2,%3}, {%4,%5,%6,%7}, {%8,%9}, {%0,%1,%2,%3};"
                 : "+f"(d[0]), "+f"(d[1]), "+f"(d[2]), "+f"(d[3])
                 : "r"(a[0]), "r"(a[1]), "r"(a[2]), "r"(a[3]), "r"(b[0]), "r"(b[1]));
}

// Fill one 128x64 bf16 tile into padded smem (4 x cp16 per thread).
__device__ __forceinline__ void fill_tile(uint32_t sdst, const __nv_bfloat16* __restrict__ g,
                                          size_t ld, int tid) {
    #pragma unroll
    for (int i=0;i<4;i++){
        int c = tid + i*256;
        int row = c>>3, col = (c&7)*8;
        cp16(sdst + (uint32_t)(row*LDS_PAD + col)*2, g + (size_t)row*ld + col);
    }
}

// Compute one BK=64 block (4 x k16) from stage smem; warp tile 64x32.
#define MMA_BK64(sa, sb)                                                          \
    do {                                                                          \
        _Pragma("unroll")                                                         \
        for (int ks = 0; ks < 4; ks++) {                                          \
            const int kk = ks*16;                                                 \
            uint32_t afr[4][4];                                                   \
            _Pragma("unroll")                                                     \
            for (int mt=0;mt<4;mt++)                                              \
                ldmatrix_x4(afr[mt], (sa) + (uint32_t)((M0 + mt*16 + a_m)*LDS_PAD + kk + a_k)*2); \
            uint32_t bfr[2][4];                                                   \
            _Pragma("unroll")                                                     \
            for (int nh=0;nh<2;nh++)                                              \
                ldmatrix_x4(bfr[nh], (sb) + (uint32_t)((N0 + nh*16 + b_n)*LDS_PAD + kk + b_k)*2); \
            _Pragma("unroll")                                                     \
            for (int mt=0;mt<4;mt++)                                              \
                _Pragma("unroll")                                                 \
                for (int nt=0;nt<4;nt++)                                          \
                    mma16816(acc[mt][nt], afr[mt], &bfr[nt>>1][(nt&1)*2]);        \
        }                                                                         \
    } while (0)

#define WARP_VARS                                                                 \
    const int w  = tid>>5, lane = tid&31;                                         \
    const int wm = w>>2, wn = w&3;                                                \
    const int M0 = wm*64, N0 = wn*32;                                             \
    const int a_m = (lane&7) + ((lane>>3)&1)*8;                                   \
    const int a_k = (lane>>4)*8;                                                  \
    const int b_n = (lane&7) + (lane>>4)*8;                                       \
    const int b_k = ((lane>>3)&1)*8;                                              \
    float acc[4][4][4];                                                           \
    _Pragma("unroll")                                                             \
    for (int i=0;i<4;i++)                                                         \
        _Pragma("unroll")                                                         \
        for (int j=0;j<4;j++)                                                     \
            _Pragma("unroll")                                                     \
            for (int r=0;r<4;r++) acc[i][j][r]=0.f;

// ---------------- 4) QKV GEMM: C = A2 @ Wt^T, BK=64, 3-stage ------------------
__global__ void __launch_bounds__(256,2) qkv_mma_kernel() {
    extern __shared__ char smdyn[];
    const int tid = threadIdx.x;
    const int bn  = blockIdx.x;     // 0..23
    const int bm  = blockIdx.y;     // 0..255
    const int m0  = bm*128;
    const __nv_bfloat16* Ag = g_a2 + (size_t)m0*KA;
    const __nv_bfloat16* Bg = g_wt + (size_t)(bn*128)*K3;
    const uint32_t sbase = smem_u32(smdyn);

    #define QKV_PF(kt) do {                                                       \
        uint32_t sa = sbase + ((kt)%NSTAGE)*STAGE_B;                              \
        fill_tile(sa,        Ag + ((kt)&31)*64, KA, tid);                         \
        fill_tile(sa+TILE_B, Bg + (kt)*64,      K3, tid);                         \
    } while(0)

    WARP_VARS;
    QKV_PF(0); cp_commit(); QKV_PF(1); cp_commit();

    #pragma unroll 1
    for (int kt = 0; kt < 48; kt++) {
        asm volatile("cp.async.wait_group 1;" ::: "memory");
        __syncthreads();
        if (kt+2 < 48) QKV_PF(kt+2);
        cp_commit();
        const uint32_t sa = sbase + (kt%NSTAGE)*STAGE_B, sb = sa + TILE_B;
        MMA_BK64(sa, sb);
    }
    #undef QKV_PF
    __syncthreads();   // smem about to be reused for epilogue staging

    // ---------------- epilogue ----------------
    const int which = bn >> 3;       // 0=q 1=k 2=v
    const int h     = bn & 7;
    const int b     = m0 >> 13;
    const int bh    = b*Hh + h;
    const int n0b   = m0 & (Nseq-1);
    const int qrow  = lane>>2;
    const int qcol  = (lane&3)*2;

    if (which == 0) {
        // q: natural layout, direct coalesced-ish stores
        #pragma unroll
        for (int mt=0; mt<4; mt++)
            #pragma unroll
            for (int r2=0; r2<2; r2++) {
                const int n_g = n0b + M0 + mt*16 + qrow + r2*8;
                #pragma unroll
                for (int nt=0; nt<4; nt++) {
                    const int e = N0 + nt*8 + qcol;
                    float v0 = acc[mt][nt][r2*2+0] + g_cbias[bn*128 + e];
                    float v1 = acc[mt][nt][r2*2+1] + g_cbias[bn*128 + e + 1];
                    v0 = 1.f/(1.f + __expf(-v0));
                    v1 = 1.f/(1.f + __expf(-v1));
                    __nv_bfloat16 h0=__float2bfloat16(v0), h1=__float2bfloat16(v1);
                    __nv_bfloat16 q0=__float2bfloat16(v0-__bfloat162float(h0)),
                                  q1=__float2bfloat16(v1-__bfloat162float(h1));
                    __nv_bfloat162 hp{h0,h1}, lp{q0,q1};
                    size_t idx = ((size_t)bh*Nseq + n_g)*HDim + e;
                    *(uint32_t*)&g_qhi[idx] = *(uint32_t*)&hp;
                    *(uint32_t*)&g_qlo[idx] = *(uint32_t*)&lp;
                }
            }
    } else {
        // k/v: transpose via smem staging, then coalesced global stores
        __nv_bfloat16* sh_hi = (__nv_bfloat16*)smdyn;            // [128 e][136]
        __nv_bfloat16* sh_lo = sh_hi + 128*136;
        #pragma unroll
        for (int mt=0; mt<4; mt++)
            #pragma unroll
            for (int r2=0; r2<2; r2++) {
                const int n_loc = M0 + mt*16 + qrow + r2*8;
                const int n_g = n0b + n_loc;
                float mfac = 1.f;
                if (which==1) mfac = g_mask[(size_t)b*Nseq + n_g] ? 0.f : 1.f;
                #pragma unroll
                for (int nt=0; nt<4; nt++) {
                    const int e = N0 + nt*8 + qcol;
                    float v0 = acc[mt][nt][r2*2+0] + g_cbias[bn*128 + e];
                    float v1 = acc[mt][nt][r2*2+1] + g_cbias[bn*128 + e + 1];
                    if (which==1) { v0 = tanhf(v0)*mfac; v1 = tanhf(v1)*mfac; }
                    __nv_bfloat16 h0=__float2bfloat16(v0), h1=__float2bfloat16(v1);
                    __nv_bfloat16 q0=__float2bfloat16(v0-__bfloat162float(h0)),
                                  q1=__float2bfloat16(v1-__bfloat162float(h1));
                    sh_hi[e*136 + n_loc]     = h0;
                    sh_hi[(e+1)*136 + n_loc] = h1;
                    sh_lo[e*136 + n_loc]     = q0;
                    sh_lo[(e+1)*136 + n_loc] = q1;
                }
            }
        __syncthreads();
        __nv_bfloat16* dh = (which==1) ? g_kth : g_vth;
        __nv_bfloat16* dl = (which==1) ? g_ktl : g_vtl;
        const size_t gbase = (size_t)bh*HDim*Nseq + n0b;
        #pragma unroll
        for (int i=0;i<8;i++){
            int c = tid + i*256;        // 2048 chunks of 16B
            int e = c>>4, n = (c&15)*8;
            float4 vh = *(float4*)&sh_hi[e*136 + n];
            float4 vl = *(float4*)&sh_lo[e*136 + n];
            *(float4*)&dh[gbase + (size_t)e*Nseq + n] = vh;
            *(float4*)&dl[gbase + (size_t)e*Nseq + n] = vl;
        }
    }
}

// ---------------- 5) kv partials via mma: kv = k^T v (3-term bf16 split) ------
__global__ void __launch_bounds__(256,2) kv_mma_kernel() {
    extern __shared__ char smdyn[];
    const int tid = threadIdx.x;
    const int ch  = blockIdx.x;     // 0..15 (n-slice of 512)
    const int bh  = blockIdx.y;     // 0..31
    const size_t obh = (size_t)bh*HDim*Nseq;
    const __nv_bfloat16* Aseg[3] = { g_kth+obh, g_ktl+obh, g_kth+obh };
    const __nv_bfloat16* Bseg[3] = { g_vth+obh, g_vth+obh, g_vtl+obh };
    const uint32_t sbase = smem_u32(smdyn);

    #define KV_PF(kt) do {                                                        \
        uint32_t sa = sbase + ((kt)%NSTAGE)*STAGE_B;                              \
        const int seg = (kt)>>3;                                                  \
        const int nc  = ch*512 + ((kt)&7)*64;                                     \
        fill_tile(sa,        Aseg[seg] + nc, Nseq, tid);                          \
        fill_tile(sa+TILE_B, Bseg[seg] + nc, Nseq, tid);                          \
    } while(0)

    WARP_VARS;
    KV_PF(0); cp_commit(); KV_PF(1); cp_commit();

    #pragma unroll 1
    for (int kt = 0; kt < 24; kt++) {
        asm volatile("cp.async.wait_group 1;" ::: "memory");
        __syncthreads();
        if (kt+2 < 24) KV_PF(kt+2);
        cp_commit();
        const uint32_t sa = sbase + (kt%NSTAGE)*STAGE_B, sb = sa + TILE_B;
        MMA_BK64(sa, sb);
    }
    #undef KV_PF

    const int qrow = lane>>2, qcol = (lane&3)*2;
    float* p = g_kvp + ((size_t)(bh*NCH2 + ch) << 14);
    #pragma unroll
    for (int mt=0; mt<4; mt++)
        #pragma unroll
        for (int r2=0; r2<2; r2++) {
            const int d = M0 + mt*16 + qrow + r2*8;
            #pragma unroll
            for (int nt=0; nt<4; nt++) {
                const int e = N0 + nt*8 + qcol;
                float2 o{acc[mt][nt][r2*2+0], acc[mt][nt][r2*2+1]};
                *(float2*)(p + (size_t)d*HDim + e) = o;
            }
        }
}

// ---------------- 6) reduce partials -> kvt2 [bh][e][hi|hi|lo over d] ---------
__global__ void kv_reduce_kernel() {
    const int bh  = blockIdx.y;
    const int idx = blockIdx.x*256 + threadIdx.x;
    float s = 0.f;
    #pragma unroll
    for (int c = 0; c < NCH2; c++)
        s += g_kvp[((size_t)(bh*NCH2 + c) << 14) + idx];
    const int d = idx >> 7, e = idx & 127;
    __nv_bfloat16 hi = __float2bfloat16(s);
    __nv_bfloat16 lo = __float2bfloat16(s - __bfloat162float(hi));
    __nv_bfloat16* base = g_kvt2 + ((size_t)bh*HDim + e)*384 + d;
    base[0]   = hi;
    base[128] = hi;
    base[256] = lo;
}

// ---------------- 7) out = q @ kv via mma (K=384), scatter fp32 ---------------
__global__ void __launch_bounds__(256,2) out_mma_kernel(float* __restrict__ out) {
    extern __shared__ char smdyn[];
    const int tid = threadIdx.x;
    const int mt0 = blockIdx.x;     // 0..63
    const int bh  = blockIdx.y;     // 0..31
    const int m0  = mt0*128;
    const size_t oq = ((size_t)bh*Nseq + m0)*HDim;
    const __nv_bfloat16* Aseg[3] = { g_qhi+oq, g_qlo+oq, g_qhi+oq };
    const __nv_bfloat16* Bg = g_kvt2 + (size_t)bh*HDim*384;
    const uint32_t sbase = smem_u32(smdyn);

    #define OUT_PF(kt) do {                                                       \
        uint32_t sa = sbase + ((kt)%NSTAGE)*STAGE_B;                              \
        const int seg = (kt)>>1;                                                  \
        fill_tile(sa,        Aseg[seg] + ((kt)&1)*64, HDim, tid);                 \
        fill_tile(sa+TILE_B, Bg + (kt)*64,            384,  tid);                 \
    } while(0)

    WARP_VARS;
    OUT_PF(0); cp_commit(); OUT_PF(1); cp_commit();

    #pragma unroll 1
    for (int kt = 0; kt < 6; kt++) {
        asm volatile("cp.async.wait_group 1;" ::: "memory");
        __syncthreads();
        if (kt+2 < 6) OUT_PF(kt+2);
        cp_commit();
        const uint32_t sa = sbase + (kt%NSTAGE)*STAGE_B, sb = sa + TILE_B;
        MMA_BK64(sa, sb);
    }
    #undef OUT_PF

    const int b = bh>>3, h = bh&7;
    const int qrow = lane>>2, qcol = (lane&3)*2;
    #pragma unroll
    for (int mt=0; mt<4; mt++)
        #pragma unroll
        for (int r2=0; r2<2; r2++) {
            const int n_g = m0 + M0 + mt*16 + qrow + r2*8;
            float* prow_p = out + ((size_t)b*Nseq + n_g)*Dm + h*HDim;
            #pragma unroll
            for (int nt=0; nt<4; nt++) {
                const int e = N0 + nt*8 + qcol;
                float2 o{acc[mt][nt][r2*2+0], acc[mt][nt][r2*2+1]};
                *(float2*)(prow_p + e) = o;
            }
        }
}

// ---------------- launch --------------------------------------------------------
extern "C" void kernel_launch(void* const* d_in, const int* in_sizes, int n_in,
                              void* d_out, int out_size) {
    const float* x = 0; const void* mask = 0; const float* w = 0;
    const float* gamma = 0; const float* beta = 0;
    for (int i = 0; i < n_in; i++) {
        int s = in_sizes[i];
        if      (s == 33554432) x    = (const float*)d_in[i];
        else if (s == 32768)    mask = d_in[i];
        else if (s == 3145728)  w    = (const float*)d_in[i];
        else if (s == 1024)     { if (!gamma) gamma = (const float*)d_in[i];
                                  else        beta  = (const float*)d_in[i]; }
    }
    float* out = (float*)d_out;

    cudaFuncSetAttribute(qkv_mma_kernel, cudaFuncAttributeMaxDynamicSharedMemorySize, SMEM_SZ);
    cudaFuncSetAttribute(kv_mma_kernel,  cudaFuncAttributeMaxDynamicSharedMemorySize, SMEM_SZ);
    cudaFuncSetAttribute(out_mma_kernel, cudaFuncAttributeMaxDynamicSharedMemorySize, SMEM_SZ);

    mask_all_kernel<<<1, 1024>>>((const unsigned int*)mask);            // 1
    ln_a2_kernel<<<Mrows, 256>>>(x);                                    // 2
    build_wt_cb_kernel<<<K3/32, 256>>>(w, gamma, beta);                 // 3
    qkv_mma_kernel<<<dim3(24, 256), 256, SMEM_SZ>>>();                  // 4 (profiled)
    kv_mma_kernel<<<dim3(NCH2, BH), 256, SMEM_SZ>>>();                  // 5
    kv_reduce_kernel<<<dim3(64, BH), 256>>>();                          // 6
    out_mma_kernel<<<dim3(64, BH), 256, SMEM_SZ>>>(out);                // 7
}

// round 8
// speedup vs baseline: 3.4415x; 1.3515x over previous
#include <cuda_runtime.h>
#include <cuda_fp16.h>
#include <cstdint>
#include <math.h>

// Problem constants
#define Bsz  4
#define Nseq 8192
#define Dm   1024
#define Hh   8
#define HDim 128
#define BH   (Bsz*Hh)        // 32
#define Mrows (Bsz*Nseq)     // 32768
#define K3   (3*Dm)          // 3072 output cols
#define KA   2048            // A split contraction length (hi|lo)
#define KW   2048            // W split contraction length (hi|hi)
#define NCH2 16              // kv n-chunks

// ---------------- scratch (static device globals; no allocations) -------------
__device__ __half g_a2[(size_t)Mrows*KA];      // 128 MiB [xh|xl]
__device__ __half g_wt[(size_t)K3*KW];         // 12 MiB per col: [wh|wh]
__device__ float g_cbias[K3];
__device__ __half g_qhi[(size_t)BH*Nseq*HDim]; // [bh][n][d]
__device__ __half g_qlo[(size_t)BH*Nseq*HDim];
__device__ __half g_kth[(size_t)BH*HDim*Nseq]; // [bh][d][n] transposed
__device__ __half g_ktl[(size_t)BH*HDim*Nseq];
__device__ __half g_vth[(size_t)BH*HDim*Nseq];
__device__ __half g_vtl[(size_t)BH*HDim*Nseq];
__device__ float g_kvp[(size_t)BH*NCH2*HDim*HDim];    // 33.5 MiB partials
__device__ __half g_kvt2[(size_t)BH*HDim*384]; // [bh][e][hi|hi|lo over d]
__device__ unsigned char g_mask[Bsz*Nseq];

// ---------------- 1) fused mask probe + normalize (single block) --------------
__global__ void mask_all_kernel(const unsigned int* __restrict__ m) {
    __shared__ unsigned int flag;
    if (threadIdx.x == 0) flag = 0u;
    __syncthreads();
    unsigned int loc = 0;
    #pragma unroll
    for (int i = threadIdx.x; i < 8192; i += 1024) loc |= (m[i] > 1u);
    if (loc) atomicOr(&flag, 1u);
    __syncthreads();
    const bool bytelay = (flag != 0u);
    for (int i = threadIdx.x; i < Bsz*Nseq; i += 1024)
        g_mask[i] = bytelay ? (((const unsigned char*)m)[i] ? 1 : 0)
                            : (((const int*)m)[i]           ? 1 : 0);
}

// ---------------- 2) fused LN stats + A2 (fp16 hi/lo) build -------------------
__global__ void ln_a2_kernel(const float* __restrict__ x) {
    int row = blockIdx.x;
    float4 v = reinterpret_cast<const float4*>(x)[(size_t)row*(Dm/4) + threadIdx.x];
    float s  = v.x+v.y+v.z+v.w;
    float ss = v.x*v.x+v.y*v.y+v.z*v.z+v.w*v.w;
    __shared__ float sh[8], sh2[8];
    __shared__ float s_mu, s_rs;
    #pragma unroll
    for (int o=16;o;o>>=1){ s+=__shfl_down_sync(~0u,s,o); ss+=__shfl_down_sync(~0u,ss,o); }
    int w = threadIdx.x>>5, l = threadIdx.x&31;
    if (l==0){ sh[w]=s; sh2[w]=ss; }
    __syncthreads();
    if (threadIdx.x < 8) {
        s = sh[threadIdx.x]; ss = sh2[threadIdx.x];
        #pragma unroll
        for (int o=4;o;o>>=1){ s+=__shfl_down_sync(0xffu,s,o); ss+=__shfl_down_sync(0xffu,ss,o); }
        if (threadIdx.x==0){
            float m = s*(1.0f/Dm);
            float var = ss*(1.0f/Dm) - m*m;
            s_mu = m; s_rs = rsqrtf(var + 1e-5f);
        }
    }
    __syncthreads();
    float mu = s_mu, rs = s_rs;
    float n0=(v.x-mu)*rs, n1=(v.y-mu)*rs, n2=(v.z-mu)*rs, n3=(v.w-mu)*rs;
    __half h0=__float2half_rn(n0), h1=__float2half_rn(n1),
           h2=__float2half_rn(n2), h3=__float2half_rn(n3);
    __half l0=__float2half_rn(n0-__half2float(h0)),
           l1=__float2half_rn(n1-__half2float(h1)),
           l2=__float2half_rn(n2-__half2float(h2)),
           l3=__float2half_rn(n3-__half2float(h3));
    __half2 hp0{h0,h1}, hp1{h2,h3}, lp0{l0,l1}, lp1{l2,l3};
    uint2 hw{*(uint32_t*)&hp0, *(uint32_t*)&hp1};
    uint2 lw{*(uint32_t*)&lp0, *(uint32_t*)&lp1};
    __half* base = g_a2 + (size_t)row*KA;
    ((uint2*)base)[threadIdx.x]          = hw;   // k in [0,1024):    hi
    ((uint2*)(base + 1024))[threadIdx.x] = lw;   // k in [1024,2048): lo
}

// ---------------- 3) Wt build + colbias (fused, deterministic) ----------------
__global__ void __launch_bounds__(256) build_wt_cb_kernel(
    const float* __restrict__ w, const float* __restrict__ gamma,
    const float* __restrict__ beta)
{
    __shared__ float tile[32][33];
    __shared__ float cbpart[8][32];
    const int n0 = blockIdx.x*32;
    const int tx = threadIdx.x & 31, ty = threadIdx.x >> 5;
    float cb = 0.f;
    for (int k0 = 0; k0 < Dm; k0 += 32) {
        #pragma unroll
        for (int r=0;r<4;r++){
            int kk = ty + r*8;
            float raw = w[(size_t)(k0+kk)*K3 + n0 + tx];
            cb += beta[k0+kk]*raw;
            tile[kk][tx] = raw * gamma[k0+kk];
        }
        __syncthreads();
        #pragma unroll
        for (int r=0;r<4;r++){
            int nn = ty + r*8;
            float val = tile[tx][nn];
            __half hi = __float2half_rn(val);
            __half* base = g_wt + (size_t)(n0+nn)*KW + k0 + tx;
            base[0]    = hi;
            base[1024] = hi;
        }
        __syncthreads();
    }
    cbpart[ty][tx] = cb;
    __syncthreads();
    if (ty == 0) {
        float s = 0.f;
        #pragma unroll
        for (int r=0;r<8;r++) s += cbpart[r][tx];
        g_cbias[n0+tx] = s;
    }
}

// ================= mma.sync building blocks ====================================
#define LDS_PAD 72
#define TILE_B  18432        // 128*72*2
#define STAGE_B 36864
#define NSTAGE  3
#define SMEM_SZ (NSTAGE*STAGE_B)   // 110592

__device__ __forceinline__ uint32_t smem_u32(const void* p) {
    uint32_t a;
    asm("{ .reg .u64 t; cvta.to.shared.u64 t, %1; cvt.u32.u64 %0, t; }" : "=r"(a) : "l"(p));
    return a;
}
__device__ __forceinline__ void cp16(uint32_t s, const void* g) {
    asm volatile("cp.async.cg.shared.global [%0], [%1], 16;" :: "r"(s), "l"(g));
}
__device__ __forceinline__ void cp_commit() {
    asm volatile("cp.async.commit_group;" ::: "memory");
}
__device__ __forceinline__ void ldmatrix_x4(uint32_t* r, uint32_t a) {
    asm volatile("ldmatrix.sync.aligned.m8n8.x4.shared.b16 {%0,%1,%2,%3}, [%4];"
                 : "=r"(r[0]), "=r"(r[1]), "=r"(r[2]), "=r"(r[3]) : "r"(a));
}
__device__ __forceinline__ void mma16816(float* d, const uint32_t* a, const uint32_t* b) {
    asm volatile("mma.sync.aligned.m16n8k16.row.col.f32.f16.f16.f32 "
                 "{%0,%1,%2,%3}, {%4,%5,%6,%7}, {%8,%9}, {%0,%1,%2,%3};"
                 : "+f"(d[0]), "+f"(d[1]), "+f"(d[2]), "+f"(d[3])
                 : "r"(a[0]), "r"(a[1]), "r"(a[2]), "r"(a[3]), "r"(b[0]), "r"(b[1]));
}

// Fill one 128x64 fp16 tile into padded smem (4 x cp16 per thread).
__device__ __forceinline__ void fill_tile(uint32_t sdst, const __half* __restrict__ g,
                                          size_t ld, int tid) {
    #pragma unroll
    for (int i=0;i<4;i++){
        int c = tid + i*256;
        int row = c>>3, col = (c&7)*8;
        cp16(sdst + (uint32_t)(row*LDS_PAD + col)*2, g + (size_t)row*ld + col);
    }
}

#define MMA_BK64(sa, sb)                                                          \
    do {                                                                          \
        _Pragma("unroll")                                                         \
        for (int ks = 0; ks < 4; ks++) {                                          \
            const int kk = ks*16;                                                 \
            uint32_t afr[4][4];                                                   \
            _Pragma("unroll")                                                     \
            for (int mt=0;mt<4;mt++)                                              \
                ldmatrix_x4(afr[mt], (sa) + (uint32_t)((M0 + mt*16 + a_m)*LDS_PAD + kk + a_k)*2); \
            uint32_t bfr[2][4];                                                   \
            _Pragma("unroll")                                                     \
            for (int nh=0;nh<2;nh++)                                              \
                ldmatrix_x4(bfr[nh], (sb) + (uint32_t)((N0 + nh*16 + b_n)*LDS_PAD + kk + b_k)*2); \
            _Pragma("unroll")                                                     \
            for (int mt=0;mt<4;mt++)                                              \
                _Pragma("unroll")                                                 \
                for (int nt=0;nt<4;nt++)                                          \
                    mma16816(acc[mt][nt], afr[mt], &bfr[nt>>1][(nt&1)*2]);        \
        }                                                                         \
    } while (0)

#define WARP_VARS                                                                 \
    const int w  = tid>>5, lane = tid&31;                                         \
    const int wm = w>>2, wn = w&3;                                                \
    const int M0 = wm*64, N0 = wn*32;                                             \
    const int a_m = (lane&7) + ((lane>>3)&1)*8;                                   \
    const int a_k = (lane>>4)*8;                                                  \
    const int b_n = (lane&7) + (lane>>4)*8;                                       \
    const int b_k = ((lane>>3)&1)*8;                                              \
    float acc[4][4][4];                                                           \
    _Pragma("unroll")                                                             \
    for (int i=0;i<4;i++)                                                         \
        _Pragma("unroll")                                                         \
        for (int j=0;j<4;j++)                                                     \
            _Pragma("unroll")                                                     \
            for (int r=0;r<4;r++) acc[i][j][r]=0.f;

// ---------------- 4) QKV GEMM: C = A2 @ Wt^T, K=2048, BK=64, 3-stage ----------
__global__ void __launch_bounds__(256,2) qkv_mma_kernel() {
    extern __shared__ char smdyn[];
    const int tid = threadIdx.x;
    const int bn  = blockIdx.x;     // 0..23
    const int bm  = blockIdx.y;     // 0..255
    const int m0  = bm*128;
    const __half* Ag = g_a2 + (size_t)m0*KA;
    const __half* Bg = g_wt + (size_t)(bn*128)*KW;
    const uint32_t sbase = smem_u32(smdyn);

    #define QKV_PF(kt) do {                                                       \
        uint32_t sa = sbase + ((kt)%NSTAGE)*STAGE_B;                              \
        fill_tile(sa,        Ag + (kt)*64, KA, tid);                              \
        fill_tile(sa+TILE_B, Bg + (kt)*64, KW, tid);                              \
    } while(0)

    WARP_VARS;
    QKV_PF(0); cp_commit(); QKV_PF(1); cp_commit();

    #pragma unroll 1
    for (int kt = 0; kt < 32; kt++) {
        asm volatile("cp.async.wait_group 1;" ::: "memory");
        __syncthreads();
        if (kt+2 < 32) QKV_PF(kt+2);
        cp_commit();
        const uint32_t sa = sbase + (kt%NSTAGE)*STAGE_B, sb = sa + TILE_B;
        MMA_BK64(sa, sb);
    }
    #undef QKV_PF
    __syncthreads();   // smem about to be reused for epilogue staging

    // ---------------- epilogue ----------------
    const int which = bn >> 3;       // 0=q 1=k 2=v
    const int h     = bn & 7;
    const int b     = m0 >> 13;
    const int bh    = b*Hh + h;
    const int n0b   = m0 & (Nseq-1);
    const int qrow  = lane>>2;
    const int qcol  = (lane&3)*2;

    if (which == 0) {
        #pragma unroll
        for (int mt=0; mt<4; mt++)
            #pragma unroll
            for (int r2=0; r2<2; r2++) {
                const int n_g = n0b + M0 + mt*16 + qrow + r2*8;
                #pragma unroll
                for (int nt=0; nt<4; nt++) {
                    const int e = N0 + nt*8 + qcol;
                    float v0 = acc[mt][nt][r2*2+0] + g_cbias[bn*128 + e];
                    float v1 = acc[mt][nt][r2*2+1] + g_cbias[bn*128 + e + 1];
                    v0 = 1.f/(1.f + __expf(-v0));
                    v1 = 1.f/(1.f + __expf(-v1));
                    __half h0=__float2half_rn(v0), h1=__float2half_rn(v1);
                    __half q0=__float2half_rn(v0-__half2float(h0)),
                           q1=__float2half_rn(v1-__half2float(h1));
                    __half2 hp{h0,h1}, lp{q0,q1};
                    size_t idx = ((size_t)bh*Nseq + n_g)*HDim + e;
                    *(uint32_t*)&g_qhi[idx] = *(uint32_t*)&hp;
                    *(uint32_t*)&g_qlo[idx] = *(uint32_t*)&lp;
                }
            }
    } else {
        // k/v: transpose via smem staging, then coalesced global stores
        __half* sh_hi = (__half*)smdyn;            // [128 e][136]
        __half* sh_lo = sh_hi + 128*136;
        #pragma unroll
        for (int mt=0; mt<4; mt++)
            #pragma unroll
            for (int r2=0; r2<2; r2++) {
                const int n_loc = M0 + mt*16 + qrow + r2*8;
                const int n_g = n0b + n_loc;
                float mfac = 1.f;
                if (which==1) mfac = g_mask[(size_t)b*Nseq + n_g] ? 0.f : 1.f;
                #pragma unroll
                for (int nt=0; nt<4; nt++) {
                    const int e = N0 + nt*8 + qcol;
                    float v0 = acc[mt][nt][r2*2+0] + g_cbias[bn*128 + e];
                    float v1 = acc[mt][nt][r2*2+1] + g_cbias[bn*128 + e + 1];
                    if (which==1) { v0 = tanhf(v0)*mfac; v1 = tanhf(v1)*mfac; }
                    __half h0=__float2half_rn(v0), h1=__float2half_rn(v1);
                    __half q0=__float2half_rn(v0-__half2float(h0)),
                           q1=__float2half_rn(v1-__half2float(h1));
                    sh_hi[e*136 + n_loc]     = h0;
                    sh_hi[(e+1)*136 + n_loc] = h1;
                    sh_lo[e*136 + n_loc]     = q0;
                    sh_lo[(e+1)*136 + n_loc] = q1;
                }
            }
        __syncthreads();
        __half* dh = (which==1) ? g_kth : g_vth;
        __half* dl = (which==1) ? g_ktl : g_vtl;
        const size_t gbase = (size_t)bh*HDim*Nseq + n0b;
        #pragma unroll
        for (int i=0;i<8;i++){
            int c = tid + i*256;        // 2048 chunks of 16B
            int e = c>>4, n = (c&15)*8;
            float4 vh = *(float4*)&sh_hi[e*136 + n];
            float4 vl = *(float4*)&sh_lo[e*136 + n];
            *(float4*)&dh[gbase + (size_t)e*Nseq + n] = vh;
            *(float4*)&dl[gbase + (size_t)e*Nseq + n] = vl;
        }
    }
}

// ---------------- 5) kv partials via mma: kv = k^T v (3-term fp16 split) ------
__global__ void __launch_bounds__(256,2) kv_mma_kernel() {
    extern __shared__ char smdyn[];
    const int tid = threadIdx.x;
    const int ch  = blockIdx.x;     // 0..15 (n-slice of 512)
    const int bh  = blockIdx.y;     // 0..31
    const size_t obh = (size_t)bh*HDim*Nseq;
    const __half* Aseg[3] = { g_kth+obh, g_ktl+obh, g_kth+obh };
    const __half* Bseg[3] = { g_vth+obh, g_vth+obh, g_vtl+obh };
    const uint32_t sbase = smem_u32(smdyn);

    #define KV_PF(kt) do {                                                        \
        uint32_t sa = sbase + ((kt)%NSTAGE)*STAGE_B;                              \
        const int seg = (kt)>>3;                                                  \
        const int nc  = ch*512 + ((kt)&7)*64;                                     \
        fill_tile(sa,        Aseg[seg] + nc, Nseq, tid);                          \
        fill_tile(sa+TILE_B, Bseg[seg] + nc, Nseq, tid);                          \
    } while(0)

    WARP_VARS;
    KV_PF(0); cp_commit(); KV_PF(1); cp_commit();

    #pragma unroll 1
    for (int kt = 0; kt < 24; kt++) {
        asm volatile("cp.async.wait_group 1;" ::: "memory");
        __syncthreads();
        if (kt+2 < 24) KV_PF(kt+2);
        cp_commit();
        const uint32_t sa = sbase + (kt%NSTAGE)*STAGE_B, sb = sa + TILE_B;
        MMA_BK64(sa, sb);
    }
    #undef KV_PF

    const int qrow = lane>>2, qcol = (lane&3)*2;
    float* p = g_kvp + ((size_t)(bh*NCH2 + ch) << 14);
    #pragma unroll
    for (int mt=0; mt<4; mt++)
        #pragma unroll
        for (int r2=0; r2<2; r2++) {
            const int d = M0 + mt*16 + qrow + r2*8;
            #pragma unroll
            for (int nt=0; nt<4; nt++) {
                const int e = N0 + nt*8 + qcol;
                float2 o{acc[mt][nt][r2*2+0], acc[mt][nt][r2*2+1]};
                *(float2*)(p + (size_t)d*HDim + e) = o;
            }
        }
}

// ---------------- 6) reduce partials -> kvt2 [bh][e][hi|hi|lo over d] ---------
__global__ void kv_reduce_kernel() {
    const int bh  = blockIdx.y;
    const int idx = blockIdx.x*256 + threadIdx.x;
    float s = 0.f;
    #pragma unroll
    for (int c = 0; c < NCH2; c++)
        s += g_kvp[((size_t)(bh*NCH2 + c) << 14) + idx];
    const int d = idx >> 7, e = idx & 127;
    __half hi = __float2half_rn(s);
    __half lo = __float2half_rn(s - __half2float(hi));
    __half* base = g_kvt2 + ((size_t)bh*HDim + e)*384 + d;
    base[0]   = hi;
    base[128] = hi;
    base[256] = lo;
}

// ---------------- 7) out = q @ kv via mma (K=384), scatter fp32 ---------------
__global__ void __launch_bounds__(256,2) out_mma_kernel(float* __restrict__ out) {
    extern __shared__ char smdyn[];
    const int tid = threadIdx.x;
    const int mt0 = blockIdx.x;     // 0..63
    const int bh  = blockIdx.y;     // 0..31
    const int m0  = mt0*128;
    const size_t oq = ((size_t)bh*Nseq + m0)*HDim;
    const __half* Aseg[3] = { g_qhi+oq, g_qlo+oq, g_qhi+oq };
    const __half* Bg = g_kvt2 + (size_t)bh*HDim*384;
    const uint32_t sbase = smem_u32(smdyn);

    #define OUT_PF(kt) do {                                                       \
        uint32_t sa = sbase + ((kt)%NSTAGE)*STAGE_B;                              \
        const int seg = (kt)>>1;                                                  \
        fill_tile(sa,        Aseg[seg] + ((kt)&1)*64, HDim, tid);                 \
        fill_tile(sa+TILE_B, Bg + (kt)*64,            384,  tid);                 \
    } while(0)

    WARP_VARS;
    OUT_PF(0); cp_commit(); OUT_PF(1); cp_commit();

    #pragma unroll 1
    for (int kt = 0; kt < 6; kt++) {
        asm volatile("cp.async.wait_group 1;" ::: "memory");
        __syncthreads();
        if (kt+2 < 6) OUT_PF(kt+2);
        cp_commit();
        const uint32_t sa = sbase + (kt%NSTAGE)*STAGE_B, sb = sa + TILE_B;
        MMA_BK64(sa, sb);
    }
    #undef OUT_PF

    const int b = bh>>3, h = bh&7;
    const int qrow = lane>>2, qcol = (lane&3)*2;
    #pragma unroll
    for (int mt=0; mt<4; mt++)
        #pragma unroll
        for (int r2=0; r2<2; r2++) {
            const int n_g = m0 + M0 + mt*16 + qrow + r2*8;
            float* prow_p = out + ((size_t)b*Nseq + n_g)*Dm + h*HDim;
            #pragma unroll
            for (int nt=0; nt<4; nt++) {
                const int e = N0 + nt*8 + qcol;
                float2 o{acc[mt][nt][r2*2+0], acc[mt][nt][r2*2+1]};
                *(float2*)(prow_p + e) = o;
            }
        }
}

// ---------------- launch --------------------------------------------------------
extern "C" void kernel_launch(void* const* d_in, const int* in_sizes, int n_in,
                              void* d_out, int out_size) {
    const float* x = 0; const void* mask = 0; const float* w = 0;
    const float* gamma = 0; const float* beta = 0;
    for (int i = 0; i < n_in; i++) {
        int s = in_sizes[i];
        if      (s == 33554432) x    = (const float*)d_in[i];
        else if (s == 32768)    mask = d_in[i];
        else if (s == 3145728)  w    = (const float*)d_in[i];
        else if (s == 1024)     { if (!gamma) gamma = (const float*)d_in[i];
                                  else        beta  = (const float*)d_in[i]; }
    }
    float* out = (float*)d_out;

    cudaFuncSetAttribute(qkv_mma_kernel, cudaFuncAttributeMaxDynamicSharedMemorySize, SMEM_SZ);
    cudaFuncSetAttribute(kv_mma_kernel,  cudaFuncAttributeMaxDynamicSharedMemorySize, SMEM_SZ);
    cudaFuncSetAttribute(out_mma_kernel, cudaFuncAttributeMaxDynamicSharedMemorySize, SMEM_SZ);

    mask_all_kernel<<<1, 1024>>>((const unsigned int*)mask);            // 1
    ln_a2_kernel<<<Mrows, 256>>>(x);                                    // 2
    build_wt_cb_kernel<<<K3/32, 256>>>(w, gamma, beta);                 // 3
    qkv_mma_kernel<<<dim3(24, 256), 256, SMEM_SZ>>>();                  // 4 (profiled)
    kv_mma_kernel<<<dim3(NCH2, BH), 256, SMEM_SZ>>>();                  // 5
    kv_reduce_kernel<<<dim3(64, BH), 256>>>();                          // 6
    out_mma_kernel<<<dim3(64, BH), 256, SMEM_SZ>>>(out);                // 7
}

// round 9
// speedup vs baseline: 5.4800x; 1.5923x over previous
#include <cuda_runtime.h>
#include <cuda_fp16.h>
#include <cstdint>
#include <math.h>

// Problem constants
#define Bsz  4
#define Nseq 8192
#define Dm   1024
#define Hh   8
#define HDim 128
#define BH   (Bsz*Hh)        // 32
#define Mrows (Bsz*Nseq)     // 32768
#define K3   (3*Dm)          // 3072 output cols
#define KA   1024            // single-segment fp16 contraction
#define NCH2 16              // kv n-chunks

// ---------------- scratch (static device globals; no allocations) -------------
__device__ __half g_a2[(size_t)Mrows*KA];      // 64 MiB  fp16(x_n)
__device__ __half g_wt[(size_t)K3*KA];         // 6 MiB   fp16(w*gamma), transposed
__device__ float g_cbias[K3];
__device__ __half g_qhi[(size_t)BH*Nseq*HDim]; // [bh][n][d]
__device__ __half g_qlo[(size_t)BH*Nseq*HDim];
__device__ __half g_kth[(size_t)BH*HDim*Nseq]; // [bh][d][n] transposed
__device__ __half g_ktl[(size_t)BH*HDim*Nseq];
__device__ __half g_vth[(size_t)BH*HDim*Nseq];
__device__ __half g_vtl[(size_t)BH*HDim*Nseq];
__device__ float g_kvp[(size_t)BH*NCH2*HDim*HDim];    // 33.5 MiB partials
__device__ __half g_kvt2[(size_t)BH*HDim*384]; // [bh][e][hi|hi|lo over d]
__device__ unsigned char g_mask[Bsz*Nseq];

// ---------------- 1) fused mask probe + normalize (single block) --------------
__global__ void mask_all_kernel(const unsigned int* __restrict__ m) {
    __shared__ unsigned int flag;
    if (threadIdx.x == 0) flag = 0u;
    __syncthreads();
    unsigned int loc = 0;
    #pragma unroll
    for (int i = threadIdx.x; i < 8192; i += 1024) loc |= (m[i] > 1u);
    if (loc) atomicOr(&flag, 1u);
    __syncthreads();
    const bool bytelay = (flag != 0u);
    for (int i = threadIdx.x; i < Bsz*Nseq; i += 1024)
        g_mask[i] = bytelay ? (((const unsigned char*)m)[i] ? 1 : 0)
                            : (((const int*)m)[i]           ? 1 : 0);
}

// ---------------- 2) fused LN stats + A2 (fp16) build -------------------------
__global__ void ln_a2_kernel(const float* __restrict__ x) {
    int row = blockIdx.x;
    float4 v = reinterpret_cast<const float4*>(x)[(size_t)row*(Dm/4) + threadIdx.x];
    float s  = v.x+v.y+v.z+v.w;
    float ss = v.x*v.x+v.y*v.y+v.z*v.z+v.w*v.w;
    __shared__ float sh[8], sh2[8];
    __shared__ float s_mu, s_rs;
    #pragma unroll
    for (int o=16;o;o>>=1){ s+=__shfl_down_sync(~0u,s,o); ss+=__shfl_down_sync(~0u,ss,o); }
    int w = threadIdx.x>>5, l = threadIdx.x&31;
    if (l==0){ sh[w]=s; sh2[w]=ss; }
    __syncthreads();
    if (threadIdx.x < 8) {
        s = sh[threadIdx.x]; ss = sh2[threadIdx.x];
        #pragma unroll
        for (int o=4;o;o>>=1){ s+=__shfl_down_sync(0xffu,s,o); ss+=__shfl_down_sync(0xffu,ss,o); }
        if (threadIdx.x==0){
            float m = s*(1.0f/Dm);
            float var = ss*(1.0f/Dm) - m*m;
            s_mu = m; s_rs = rsqrtf(var + 1e-5f);
        }
    }
    __syncthreads();
    float mu = s_mu, rs = s_rs;
    float n0=(v.x-mu)*rs, n1=(v.y-mu)*rs, n2=(v.z-mu)*rs, n3=(v.w-mu)*rs;
    __half2 hp0{__float2half_rn(n0), __float2half_rn(n1)};
    __half2 hp1{__float2half_rn(n2), __float2half_rn(n3)};
    uint2 hw{*(uint32_t*)&hp0, *(uint32_t*)&hp1};
    ((uint2*)(g_a2 + (size_t)row*KA))[threadIdx.x] = hw;
}

// ---------------- 3) Wt build + colbias (fused, deterministic) ----------------
__global__ void __launch_bounds__(256) build_wt_cb_kernel(
    const float* __restrict__ w, const float* __restrict__ gamma,
    const float* __restrict__ beta)
{
    __shared__ float tile[32][33];
    __shared__ float cbpart[8][32];
    const int n0 = blockIdx.x*32;
    const int tx = threadIdx.x & 31, ty = threadIdx.x >> 5;
    float cb = 0.f;
    for (int k0 = 0; k0 < Dm; k0 += 32) {
        #pragma unroll
        for (int r=0;r<4;r++){
            int kk = ty + r*8;
            float raw = w[(size_t)(k0+kk)*K3 + n0 + tx];
            cb += beta[k0+kk]*raw;
            tile[kk][tx] = raw * gamma[k0+kk];
        }
        __syncthreads();
        #pragma unroll
        for (int r=0;r<4;r++){
            int nn = ty + r*8;
            g_wt[(size_t)(n0+nn)*KA + k0 + tx] = __float2half_rn(tile[tx][nn]);
        }
        __syncthreads();
    }
    cbpart[ty][tx] = cb;
    __syncthreads();
    if (ty == 0) {
        float s = 0.f;
        #pragma unroll
        for (int r=0;r<8;r++) s += cbpart[r][tx];
        g_cbias[n0+tx] = s;
    }
}

// ================= mma.sync building blocks ====================================
#define LDS_PAD 72
#define TILE_B  18432        // 128*72*2
#define STAGE_B 36864
#define NSTAGE  3
#define SMEM_SZ (NSTAGE*STAGE_B)   // 110592

__device__ __forceinline__ uint32_t smem_u32(const void* p) {
    uint32_t a;
    asm("{ .reg .u64 t; cvta.to.shared.u64 t, %1; cvt.u32.u64 %0, t; }" : "=r"(a) : "l"(p));
    return a;
}
__device__ __forceinline__ void cp16(uint32_t s, const void* g) {
    asm volatile("cp.async.cg.shared.global [%0], [%1], 16;" :: "r"(s), "l"(g));
}
__device__ __forceinline__ void cp_commit() {
    asm volatile("cp.async.commit_group;" ::: "memory");
}
__device__ __forceinline__ void ldmatrix_x4(uint32_t* r, uint32_t a) {
    asm volatile("ldmatrix.sync.aligned.m8n8.x4.shared.b16 {%0,%1,%2,%3}, [%4];"
                 : "=r"(r[0]), "=r"(r[1]), "=r"(r[2]), "=r"(r[3]) : "r"(a));
}
__device__ __forceinline__ void mma16816(float* d, const uint32_t* a, const uint32_t* b) {
    asm volatile("mma.sync.aligned.m16n8k16.row.col.f32.f16.f16.f32 "
                 "{%0,%1,%2,%3}, {%4,%5,%6,%7}, {%8,%9}, {%0,%1,%2,%3};"
                 : "+f"(d[0]), "+f"(d[1]), "+f"(d[2]), "+f"(d[3])
                 : "r"(a[0]), "r"(a[1]), "r"(a[2]), "r"(a[3]), "r"(b[0]), "r"(b[1]));
}

// Fill one 128x64 fp16 tile into padded smem (4 x cp16 per thread).
__device__ __forceinline__ void fill_tile(uint32_t sdst, const __half* __restrict__ g,
                                          size_t ld, int tid) {
    #pragma unroll
    for (int i=0;i<4;i++){
        int c = tid + i*256;
        int row = c>>3, col = (c&7)*8;
        cp16(sdst + (uint32_t)(row*LDS_PAD + col)*2, g + (size_t)row*ld + col);
    }
}

#define MMA_BK64(sa, sb)                                                          \
    do {                                                                          \
        _Pragma("unroll")                                                         \
        for (int ks = 0; ks < 4; ks++) {                                          \
            const int kk = ks*16;                                                 \
            uint32_t afr[4][4];                                                   \
            _Pragma("unroll")                                                     \
            for (int mt=0;mt<4;mt++)                                              \
                ldmatrix_x4(afr[mt], (sa) + (uint32_t)((M0 + mt*16 + a_m)*LDS_PAD + kk + a_k)*2); \
            uint32_t bfr[2][4];                                                   \
            _Pragma("unroll")                                                     \
            for (int nh=0;nh<2;nh++)                                              \
                ldmatrix_x4(bfr[nh], (sb) + (uint32_t)((N0 + nh*16 + b_n)*LDS_PAD + kk + b_k)*2); \
            _Pragma("unroll")                                                     \
            for (int mt=0;mt<4;mt++)                                              \
                _Pragma("unroll")                                                 \
                for (int nt=0;nt<4;nt++)                                          \
                    mma16816(acc[mt][nt], afr[mt], &bfr[nt>>1][(nt&1)*2]);        \
        }                                                                         \
    } while (0)

#define WARP_VARS                                                                 \
    const int w  = tid>>5, lane = tid&31;                                         \
    const int wm = w>>2, wn = w&3;                                                \
    const int M0 = wm*64, N0 = wn*32;                                             \
    const int a_m = (lane&7) + ((lane>>3)&1)*8;                                   \
    const int a_k = (lane>>4)*8;                                                  \
    const int b_n = (lane&7) + (lane>>4)*8;                                       \
    const int b_k = ((lane>>3)&1)*8;                                              \
    float acc[4][4][4];                                                           \
    _Pragma("unroll")                                                             \
    for (int i=0;i<4;i++)                                                         \
        _Pragma("unroll")                                                         \
        for (int j=0;j<4;j++)                                                     \
            _Pragma("unroll")                                                     \
            for (int r=0;r<4;r++) acc[i][j][r]=0.f;

// ---------------- 4) QKV GEMM: C = A2 @ Wt^T, K=1024, BK=64, 3-stage ----------
__global__ void __launch_bounds__(256,2) qkv_mma_kernel() {
    extern __shared__ char smdyn[];
    const int tid = threadIdx.x;
    const int bn  = blockIdx.x;     // 0..23
    const int bm  = blockIdx.y;     // 0..255
    const int m0  = bm*128;
    const __half* Ag = g_a2 + (size_t)m0*KA;
    const __half* Bg = g_wt + (size_t)(bn*128)*KA;
    const uint32_t sbase = smem_u32(smdyn);

    #define QKV_PF(kt) do {                                                       \
        uint32_t sa = sbase + ((kt)%NSTAGE)*STAGE_B;                              \
        fill_tile(sa,        Ag + (kt)*64, KA, tid);                              \
        fill_tile(sa+TILE_B, Bg + (kt)*64, KA, tid);                              \
    } while(0)

    WARP_VARS;
    QKV_PF(0); cp_commit(); QKV_PF(1); cp_commit();

    #pragma unroll 1
    for (int kt = 0; kt < 16; kt++) {
        asm volatile("cp.async.wait_group 1;" ::: "memory");
        __syncthreads();
        if (kt+2 < 16) QKV_PF(kt+2);
        cp_commit();
        const uint32_t sa = sbase + (kt%NSTAGE)*STAGE_B, sb = sa + TILE_B;
        MMA_BK64(sa, sb);
    }
    #undef QKV_PF
    __syncthreads();   // smem about to be reused for epilogue staging

    // ---------------- epilogue ----------------
    const int which = bn >> 3;       // 0=q 1=k 2=v
    const int h     = bn & 7;
    const int b     = m0 >> 13;
    const int bh    = b*Hh + h;
    const int n0b   = m0 & (Nseq-1);
    const int qrow  = lane>>2;
    const int qcol  = (lane&3)*2;

    if (which == 0) {
        #pragma unroll
        for (int mt=0; mt<4; mt++)
            #pragma unroll
            for (int r2=0; r2<2; r2++) {
                const int n_g = n0b + M0 + mt*16 + qrow + r2*8;
                #pragma unroll
                for (int nt=0; nt<4; nt++) {
                    const int e = N0 + nt*8 + qcol;
                    float v0 = acc[mt][nt][r2*2+0] + g_cbias[bn*128 + e];
                    float v1 = acc[mt][nt][r2*2+1] + g_cbias[bn*128 + e + 1];
                    v0 = 1.f/(1.f + __expf(-v0));
                    v1 = 1.f/(1.f + __expf(-v1));
                    __half h0=__float2half_rn(v0), h1=__float2half_rn(v1);
                    __half q0=__float2half_rn(v0-__half2float(h0)),
                           q1=__float2half_rn(v1-__half2float(h1));
                    __half2 hp{h0,h1}, lp{q0,q1};
                    size_t idx = ((size_t)bh*Nseq + n_g)*HDim + e;
                    *(uint32_t*)&g_qhi[idx] = *(uint32_t*)&hp;
                    *(uint32_t*)&g_qlo[idx] = *(uint32_t*)&lp;
                }
            }
    } else {
        // k/v: transpose via smem staging, then coalesced global stores
        __half* sh_hi = (__half*)smdyn;            // [128 e][136]
        __half* sh_lo = sh_hi + 128*136;
        #pragma unroll
        for (int mt=0; mt<4; mt++)
            #pragma unroll
            for (int r2=0; r2<2; r2++) {
                const int n_loc = M0 + mt*16 + qrow + r2*8;
                const int n_g = n0b + n_loc;
                float mfac = 1.f;
                if (which==1) mfac = g_mask[(size_t)b*Nseq + n_g] ? 0.f : 1.f;
                #pragma unroll
                for (int nt=0; nt<4; nt++) {
                    const int e = N0 + nt*8 + qcol;
                    float v0 = acc[mt][nt][r2*2+0] + g_cbias[bn*128 + e];
                    float v1 = acc[mt][nt][r2*2+1] + g_cbias[bn*128 + e + 1];
                    if (which==1) { v0 = tanhf(v0)*mfac; v1 = tanhf(v1)*mfac; }
                    __half h0=__float2half_rn(v0), h1=__float2half_rn(v1);
                    __half q0=__float2half_rn(v0-__half2float(h0)),
                           q1=__float2half_rn(v1-__half2float(h1));
                    sh_hi[e*136 + n_loc]     = h0;
                    sh_hi[(e+1)*136 + n_loc] = h1;
                    sh_lo[e*136 + n_loc]     = q0;
                    sh_lo[(e+1)*136 + n_loc] = q1;
                }
            }
        __syncthreads();
        __half* dh = (which==1) ? g_kth : g_vth;
        __half* dl = (which==1) ? g_ktl : g_vtl;
        const size_t gbase = (size_t)bh*HDim*Nseq + n0b;
        #pragma unroll
        for (int i=0;i<8;i++){
            int c = tid + i*256;        // 2048 chunks of 16B
            int e = c>>4, n = (c&15)*8;
            float4 vh = *(float4*)&sh_hi[e*136 + n];
            float4 vl = *(float4*)&sh_lo[e*136 + n];
            *(float4*)&dh[gbase + (size_t)e*Nseq + n] = vh;
            *(float4*)&dl[gbase + (size_t)e*Nseq + n] = vl;
        }
    }
}

// ---------------- 5) kv partials via mma: kv = k^T v (3-term fp16 split) ------
__global__ void __launch_bounds__(256,2) kv_mma_kernel() {
    extern __shared__ char smdyn[];
    const int tid = threadIdx.x;
    const int ch  = blockIdx.x;     // 0..15 (n-slice of 512)
    const int bh  = blockIdx.y;     // 0..31
    const size_t obh = (size_t)bh*HDim*Nseq;
    const __half* Aseg[3] = { g_kth+obh, g_ktl+obh, g_kth+obh };
    const __half* Bseg[3] = { g_vth+obh, g_vth+obh, g_vtl+obh };
    const uint32_t sbase = smem_u32(smdyn);

    #define KV_PF(kt) do {                                                        \
        uint32_t sa = sbase + ((kt)%NSTAGE)*STAGE_B;                              \
        const int seg = (kt)>>3;                                                  \
        const int nc  = ch*512 + ((kt)&7)*64;                                     \
        fill_tile(sa,        Aseg[seg] + nc, Nseq, tid);                          \
        fill_tile(sa+TILE_B, Bseg[seg] + nc, Nseq, tid);                          \
    } while(0)

    WARP_VARS;
    KV_PF(0); cp_commit(); KV_PF(1); cp_commit();

    #pragma unroll 1
    for (int kt = 0; kt < 24; kt++) {
        asm volatile("cp.async.wait_group 1;" ::: "memory");
        __syncthreads();
        if (kt+2 < 24) KV_PF(kt+2);
        cp_commit();
        const uint32_t sa = sbase + (kt%NSTAGE)*STAGE_B, sb = sa + TILE_B;
        MMA_BK64(sa, sb);
    }
    #undef KV_PF

    const int qrow = lane>>2, qcol = (lane&3)*2;
    float* p = g_kvp + ((size_t)(bh*NCH2 + ch) << 14);
    #pragma unroll
    for (int mt=0; mt<4; mt++)
        #pragma unroll
        for (int r2=0; r2<2; r2++) {
            const int d = M0 + mt*16 + qrow + r2*8;
            #pragma unroll
            for (int nt=0; nt<4; nt++) {
                const int e = N0 + nt*8 + qcol;
                float2 o{acc[mt][nt][r2*2+0], acc[mt][nt][r2*2+1]};
                *(float2*)(p + (size_t)d*HDim + e) = o;
            }
        }
}

// ---------------- 6) reduce partials -> kvt2 [bh][e][hi|hi|lo over d] ---------
__global__ void kv_reduce_kernel() {
    const int bh  = blockIdx.y;
    const int idx = blockIdx.x*256 + threadIdx.x;
    float s = 0.f;
    #pragma unroll
    for (int c = 0; c < NCH2; c++)
        s += g_kvp[((size_t)(bh*NCH2 + c) << 14) + idx];
    const int d = idx >> 7, e = idx & 127;
    __half hi = __float2half_rn(s);
    __half lo = __float2half_rn(s - __half2float(hi));
    __half* base = g_kvt2 + ((size_t)bh*HDim + e)*384 + d;
    base[0]   = hi;
    base[128] = hi;
    base[256] = lo;
}

// ---------------- 7) out = q @ kv via mma (K=384), scatter fp32 ---------------
__global__ void __launch_bounds__(256,2) out_mma_kernel(float* __restrict__ out) {
    extern __shared__ char smdyn[];
    const int tid = threadIdx.x;
    const int mt0 = blockIdx.x;     // 0..63
    const int bh  = blockIdx.y;     // 0..31
    const int m0  = mt0*128;
    const size_t oq = ((size_t)bh*Nseq + m0)*HDim;
    const __half* Aseg[3] = { g_qhi+oq, g_qlo+oq, g_qhi+oq };
    const __half* Bg = g_kvt2 + (size_t)bh*HDim*384;
    const uint32_t sbase = smem_u32(smdyn);

    #define OUT_PF(kt) do {                                                       \
        uint32_t sa = sbase + ((kt)%NSTAGE)*STAGE_B;                              \
        const int seg = (kt)>>1;                                                  \
        fill_tile(sa,        Aseg[seg] + ((kt)&1)*64, HDim, tid);                 \
        fill_tile(sa+TILE_B, Bg + (kt)*64,            384,  tid);                 \
    } while(0)

    WARP_VARS;
    OUT_PF(0); cp_commit(); OUT_PF(1); cp_commit();

    #pragma unroll 1
    for (int kt = 0; kt < 6; kt++) {
        asm volatile("cp.async.wait_group 1;" ::: "memory");
        __syncthreads();
        if (kt+2 < 6) OUT_PF(kt+2);
        cp_commit();
        const uint32_t sa = sbase + (kt%NSTAGE)*STAGE_B, sb = sa + TILE_B;
        MMA_BK64(sa, sb);
    }
    #undef OUT_PF

    const int b = bh>>3, h = bh&7;
    const int qrow = lane>>2, qcol = (lane&3)*2;
    #pragma unroll
    for (int mt=0; mt<4; mt++)
        #pragma unroll
        for (int r2=0; r2<2; r2++) {
            const int n_g = m0 + M0 + mt*16 + qrow + r2*8;
            float* prow_p = out + ((size_t)b*Nseq + n_g)*Dm + h*HDim;
            #pragma unroll
            for (int nt=0; nt<4; nt++) {
                const int e = N0 + nt*8 + qcol;
                float2 o{acc[mt][nt][r2*2+0], acc[mt][nt][r2*2+1]};
                *(float2*)(prow_p + e) = o;
            }
        }
}

// ---------------- launch --------------------------------------------------------
extern "C" void kernel_launch(void* const* d_in, const int* in_sizes, int n_in,
                              void* d_out, int out_size) {
    const float* x = 0; const void* mask = 0; const float* w = 0;
    const float* gamma = 0; const float* beta = 0;
    for (int i = 0; i < n_in; i++) {
        int s = in_sizes[i];
        if      (s == 33554432) x    = (const float*)d_in[i];
        else if (s == 32768)    mask = d_in[i];
        else if (s == 3145728)  w    = (const float*)d_in[i];
        else if (s == 1024)     { if (!gamma) gamma = (const float*)d_in[i];
                                  else        beta  = (const float*)d_in[i]; }
    }
    float* out = (float*)d_out;

    cudaFuncSetAttribute(qkv_mma_kernel, cudaFuncAttributeMaxDynamicSharedMemorySize, SMEM_SZ);
    cudaFuncSetAttribute(kv_mma_kernel,  cudaFuncAttributeMaxDynamicSharedMemorySize, SMEM_SZ);
    cudaFuncSetAttribute(out_mma_kernel, cudaFuncAttributeMaxDynamicSharedMemorySize, SMEM_SZ);

    mask_all_kernel<<<1, 1024>>>((const unsigned int*)mask);            // 1
    ln_a2_kernel<<<Mrows, 256>>>(x);                                    // 2
    build_wt_cb_kernel<<<K3/32, 256>>>(w, gamma, beta);                 // 3
    qkv_mma_kernel<<<dim3(24, 256), 256, SMEM_SZ>>>();                  // 4 (profiled)
    kv_mma_kernel<<<dim3(NCH2, BH), 256, SMEM_SZ>>>();                  // 5
    kv_reduce_kernel<<<dim3(64, BH), 256>>>();                          // 6
    out_mma_kernel<<<dim3(64, BH), 256, SMEM_SZ>>>(out);                // 7
}